// round 5
// baseline (speedup 1.0000x reference)
#include <cuda_runtime.h>
#include <math.h>
#include <stddef.h>
#include <stdint.h>

// Problem constants: Dur=32, Dim=256, T=528
#define TT 528

// Scratch (device globals: allocation-free)
__device__ float g_ypart[2][256 * TT];  // conv partial sums, layout [t][o]
__device__ float g_u[TT];
__device__ float g_a[4 * TT];           // a_w[q] = col-sums of opw rows 128w..
__device__ float g_m[4 * TT];           // m_w[t] = sum_q a_w[q]*ipw[2T+q, t]

// k_conv shared: xs1/xs2 transposed x copies + NBUF weight buffers
#define XR 34                            // padded row stride (floats), 8B-divisible
#define XS1_FLOATS (128 * XR)            // 4352
#define XS_TOTAL (2 * XS1_FLOATS)        // 8704 floats = 34816 B
#define WS_MAX_BYTES 73728               // max: NBUF=2 x 256 rows x SP=36 x 4B
#define SMEM_BYTES (XS_TOTAL * 4 + WS_MAX_BYTES)

__device__ __forceinline__ uint32_t smem_u32(const void* p) {
    return (uint32_t)__cvta_generic_to_shared(p);
}
__device__ __forceinline__ unsigned long long pk2(float lo, float hi) {
    unsigned long long r;
    asm("mov.b64 %0, {%1, %2};" : "=l"(r) : "f"(lo), "f"(hi));
    return r;
}
__device__ __forceinline__ void upk2(float& lo, float& hi, unsigned long long v) {
    asm("mov.b64 {%0, %1}, %2;" : "=f"(lo), "=f"(hi) : "l"(v));
}
__device__ __forceinline__ void fma2(unsigned long long& d,
                                     unsigned long long a, unsigned long long b) {
    asm("fma.rn.f32x2 %0, %1, %2, %0;" : "+l"(d) : "l"(a), "l"(b));
}

// ---------------------------------------------------------------------------
// Stage 1: per-branch conv, templated on (K, L), f32x2 over t-pairs.
// Block: 256 threads = 32 o x 8 g. xs1[il][j] = x(tau=j, ch), xs2 = shifted
// copy (tau=j+1) so both even- and odd-tap x pairs are aligned LDS.64.
// Weights cp.async pipelined with depth NBUF (deeper for light K).
// ---------------------------------------------------------------------------
template<int K, int L>
__device__ __forceinline__ void conv_branch(
    const float* __restrict__ wB,
    const float* __restrict__ xs1, const float* __restrict__ xs2,
    float* __restrict__ ws,
    int otile, int ihalf, int tid,
    float* __restrict__ yout)
{
    constexpr int C4 = (K + 3) / 4;
    constexpr int SP = C4 * 4 + ((C4 & 1) ? 8 : 4);   // floats, %8==4
    constexpr int NBUF = (K <= 8) ? 4 : ((K <= 16) ? 3 : 2);
    constexpr int BUF = 256 * SP;
    constexpr int L2 = L / 2;

    const int g = tid & 7;
    const int o = otile * 32 + (tid >> 3);

    unsigned long long acc2[L2 > 0 ? L2 : 1];
#pragma unroll
    for (int t = 0; t < L2; t++) acc2[t] = 0ull;
    float accT = 0.0f;

    auto stage = [&](int ii) {
        const int ibase = ihalf * 128 + ii * 8;
        const uint32_t wsb = smem_u32(ws + (ii % NBUF) * BUF);
#pragma unroll
        for (int k = 0; k < C4; k++) {
            int idx = tid + 256 * k;
            int r = idx / C4;
            int c = idx - r * C4;
            const float* src = wB + (size_t)(otile * 32 + (r >> 3)) * 8192
                                  + (size_t)(ibase + (r & 7)) * 32 + c * 4;
            asm volatile("cp.async.cg.shared.global [%0], [%1], 16;"
                         :: "r"(wsb + (uint32_t)(r * SP + c * 4) * 4), "l"(src));
        }
        asm volatile("cp.async.commit_group;");
    };

#pragma unroll
    for (int p = 0; p < NBUF - 1; p++) stage(p);

    for (int ii = 0; ii < 16; ++ii) {
        if (ii <= 16 - NBUF + 1) {
            asm volatile("cp.async.wait_group %0;" :: "n"(NBUF - 2));
        } else {
            asm volatile("cp.async.wait_group 0;");
        }
        __syncthreads();                 // readers of iter ii-1 done; buf ii ready
        if (ii + NBUF - 1 < 16) stage(ii + NBUF - 1);

        const int il = ii * 8 + g;
        const float* x1r = xs1 + il * XR;
        const float* x2r = xs2 + il * XR;

        // weight row (private, conflict-free) -> packed ww
        const float* wrow = ws + (ii % NBUF) * BUF + tid * SP;
        float wv[C4 * 4];
#pragma unroll
        for (int c = 0; c < C4; c++) {
            float4 w4 = *reinterpret_cast<const float4*>(wrow + c * 4);
            wv[c * 4 + 0] = w4.x; wv[c * 4 + 1] = w4.y;
            wv[c * 4 + 2] = w4.z; wv[c * 4 + 3] = w4.w;
        }
        unsigned long long ww[K > 1 ? K : 1];
        if constexpr (L2 > 0) {
#pragma unroll
            for (int h = 0; h < K; h++) ww[h] = pk2(wv[h], wv[h]);
        }

        // packed K*L/2 f32x2 block; x operands straight from (CSE'd) LDS.64
#pragma unroll
        for (int tp = 0; tp < L2; tp++) {
#pragma unroll
            for (int h = 0; h < K; h++) {
                unsigned long long xv = (h & 1)
                    ? *reinterpret_cast<const unsigned long long*>(x2r + 2 * (tp + (h - 1) / 2))
                    : *reinterpret_cast<const unsigned long long*>(x1r + 2 * (tp + h / 2));
                fma2(acc2[tp], xv, ww[h]);
            }
        }
        if constexpr (L & 1) {
#pragma unroll
            for (int h = 0; h < K; h++)
                accT = fmaf(x1r[L - 1 + h], wv[h], accT);
        }
        __syncwarp();
    }

    // unpack, reduce over the 8 i-lanes via warp shuffles, store
#pragma unroll
    for (int tp = 0; tp < L2; tp++) {
        float a0, a1;
        upk2(a0, a1, acc2[tp]);
#pragma unroll
        for (int m = 1; m <= 4; m <<= 1) {
            a0 += __shfl_xor_sync(0xffffffffu, a0, m);
            a1 += __shfl_xor_sync(0xffffffffu, a1, m);
        }
        if (g == 0) {
            yout[(2 * tp) * 256 + o] = a0;
            yout[(2 * tp + 1) * 256 + o] = a1;
        }
    }
    if constexpr (L & 1) {
#pragma unroll
        for (int m = 1; m <= 4; m <<= 1)
            accT += __shfl_xor_sync(0xffffffffu, accT, m);
        if (g == 0) yout[(L - 1) * 256 + o] = accT;
    }
}

template<int B>
__device__ __forceinline__ void dispatch_branch(
    int b, const float* __restrict__ cw,
    const float* __restrict__ xs1, const float* __restrict__ xs2,
    float* __restrict__ ws, int otile, int ihalf, int tid)
{
    if (b == B) {
        constexpr int TOFF = B * 32 - (B * (B - 1)) / 2;
        conv_branch<B + 1, 32 - B>(cw + (size_t)B * (256 * 256 * 32),
                                   xs1, xs2, ws, otile, ihalf, tid,
                                   &g_ypart[ihalf][TOFF * 256]);
    } else if constexpr (B < 31) {
        dispatch_branch<B + 1>(b, cw, xs1, xs2, ws, otile, ihalf, tid);
    }
}

__global__ void __launch_bounds__(256) k_conv(
    const float* __restrict__ x, const float* __restrict__ cw)
{
    extern __shared__ float smem[];
    float* xs1 = smem;
    float* xs2 = smem + XS1_FLOATS;
    float* ws  = smem + XS_TOTAL;

    const int tid = threadIdx.x;
    const int ko = blockIdx.x >> 4;
    // heavy-first: K*L max at b=15,16
    const int b = (ko & 1) ? (16 + (ko >> 1)) : (15 - (ko >> 1));
    const int sub = blockIdx.x & 15;
    const int otile = sub >> 1;
    const int ihalf = sub & 1;

    // transpose-stage x: xs1[il][j] = x(j, ihalf*128+il); xs2 shifted by one tau
    for (int idx = tid; idx < 4096; idx += 256) {
        int j = idx >> 7;
        int il = idx & 127;
        float v = x[j * 256 + ihalf * 128 + il];
        xs1[il * XR + j] = v;
        if (j > 0) xs2[il * XR + (j - 1)] = v;
    }
    __syncthreads();

    dispatch_branch<0>(b, cw, xs1, xs2, ws, otile, ihalf, tid);
}

// ---------------------------------------------------------------------------
// Stage 2 (fused): per-branch bias + exact gelu + mean/var + ln + channel-sum.
// ---------------------------------------------------------------------------
__global__ void __launch_bounds__(256) k_post(
    const float* __restrict__ conv_b,
    const float* __restrict__ lnw, const float* __restrict__ lnb)
{
    const int b = blockIdx.x;
    const int tid = threadIdx.x;
    const int L = 32 - b;
    const int toff = b * 32 - (b * (b - 1)) / 2;
    const int o = tid;

    const float* p0 = &g_ypart[0][toff * 256 + o];
    const float* p1 = &g_ypart[1][toff * 256 + o];
    const float cb = conv_b[b * 256 + o];

    float v[32];
    float s = 0.0f, s2 = 0.0f;
#pragma unroll
    for (int t = 0; t < 32; t++) {
        if (t < L) {
            float val = p0[t * 256] + p1[t * 256] + cb;
            float ge = 0.5f * val * (1.0f + erff(val * 0.70710678118654752440f));
            v[t] = ge;
            s += ge;
            s2 += ge * ge;
        }
    }

    __shared__ float sh[256];
    __shared__ float sh2[256];
    sh[tid] = s; sh2[tid] = s2;
    __syncthreads();
    for (int st = 128; st > 0; st >>= 1) {
        if (tid < st) { sh[tid] += sh[tid + st]; sh2[tid] += sh2[tid + st]; }
        __syncthreads();
    }
    __shared__ float s_mu, s_rs;
    if (tid == 0) {
        float inv = 1.0f / (float)(256 * L);
        float mu = sh[0] * inv;
        float var = sh2[0] * inv - mu * mu;
        s_mu = mu;
        s_rs = rsqrtf(var + 1e-5f);
    }
    __syncthreads();
    const float mu = s_mu, rs = s_rs;

    const float* lwp = lnw + ((size_t)b * 256 + o) * 32;
    const float* lbp = lnb + ((size_t)b * 256 + o) * 32;
    const int warp = tid >> 5, lane = tid & 31;
    __shared__ float red[32][9];

#pragma unroll
    for (int t = 0; t < 32; t++) {
        float c = 0.0f;
        if (t < L) c = fmaf((v[t] - mu) * rs, lwp[t], lbp[t]);
        c += __shfl_xor_sync(0xffffffffu, c, 16);
        c += __shfl_xor_sync(0xffffffffu, c, 8);
        c += __shfl_xor_sync(0xffffffffu, c, 4);
        c += __shfl_xor_sync(0xffffffffu, c, 2);
        c += __shfl_xor_sync(0xffffffffu, c, 1);
        if (lane == 0) red[t][warp] = c;
    }
    __syncthreads();
    if (tid < L) {
        float u = 0.0f;
#pragma unroll
        for (int w = 0; w < 8; w++) u += red[tid][w];
        g_u[toff + tid] = u;
    }
}

// ---------------------------------------------------------------------------
// k_a (input-only): a_w[q] = sum_{j<32} opw[128w+j, q].  Two launches (part
// 0: w=0,1; part 1: w=2,3) of grid 4 so k_conv lands at launch index 4.
// ---------------------------------------------------------------------------
__global__ void __launch_bounds__(256) k_a(const float* __restrict__ opw, int part)
{
    const int w = part * 2 + (blockIdx.x >> 1);
    const int half = blockIdx.x & 1;
    const int tid = threadIdx.x;
    for (int qi = tid; qi < 264; qi += 256) {
        int q = half * 264 + qi;
        float a = 0.0f;
        const float* base = opw + (size_t)(128 * w) * TT + q;
#pragma unroll
        for (int j = 0; j < 32; j++) a += base[(size_t)j * TT];
        g_a[w * TT + q] = a;
    }
}

// ---------------------------------------------------------------------------
// k_m (input-only): m_w[t] = sum_q a_w[q] * ipw[2T+q, t].
// grid 9 x 256: block covers 64 t; tid = w*64 + tl.
// ---------------------------------------------------------------------------
__global__ void __launch_bounds__(256) k_m(const float* __restrict__ ipw)
{
    const int tid = threadIdx.x;
    const int w = tid >> 6;
    const int tl = tid & 63;
    const int t = blockIdx.x * 64 + tl;

    __shared__ float a_s[4 * TT];
    for (int i = tid; i < 4 * TT; i += 256) a_s[i] = g_a[i];
    __syncthreads();

    if (t < TT) {
        const float* aw = a_s + w * TT;
        const float* col = ipw + (size_t)(2 * TT) * TT + t;
        float acc = 0.0f;
#pragma unroll 8
        for (int q = 0; q < TT; q++) acc += aw[q] * col[(size_t)q * TT];
        g_m[w * TT + t] = acc;
    }
}

// ---------------------------------------------------------------------------
// k_fin: out[0,w,d] = (1/32)*( u.m_w + 256*(a_w . ipb[2T:]) + 256*sum_j opb )
// ---------------------------------------------------------------------------
__global__ void __launch_bounds__(256) k_fin(
    const float* __restrict__ ipb, const float* __restrict__ opb,
    float* __restrict__ out)
{
    const int tid = threadIdx.x;
    __shared__ float sh[256];
    __shared__ float tot[4];
#pragma unroll
    for (int w = 0; w < 4; w++) {
        float p = 0.0f;
        for (int t = tid; t < TT; t += 256)
            p += g_u[t] * g_m[w * TT + t] + 256.0f * g_a[w * TT + t] * ipb[2 * TT + t];
        if (tid < 32) p += 256.0f * opb[128 * w + tid];
        sh[tid] = p;
        __syncthreads();
        for (int st = 128; st > 0; st >>= 1) {
            if (tid < st) sh[tid] += sh[tid + st];
            __syncthreads();
        }
        if (tid == 0) tot[w] = sh[0] * (1.0f / 32.0f);
        __syncthreads();
    }
#pragma unroll
    for (int w = 0; w < 4; w++) out[w * 256 + tid] = tot[w];
}

// ---------------------------------------------------------------------------
extern "C" void kernel_launch(void* const* d_in, const int* in_sizes, int n_in,
                              void* d_out, int out_size)
{
    const float* x      = (const float*)d_in[0];
    const float* conv_w = (const float*)d_in[1];
    const float* conv_b = (const float*)d_in[2];
    const float* ln_w   = (const float*)d_in[3];
    const float* ln_b   = (const float*)d_in[4];
    const float* ipw    = (const float*)d_in[5];
    const float* ipb    = (const float*)d_in[6];
    const float* opw    = (const float*)d_in[7];
    const float* opb    = (const float*)d_in[8];
    float* out = (float*)d_out;

    cudaFuncSetAttribute(k_conv, cudaFuncAttributeMaxDynamicSharedMemorySize,
                         SMEM_BYTES);

    k_a   <<<4, 256>>>(opw, 0);               // launch 1
    k_a   <<<4, 256>>>(opw, 1);               // launch 2
    k_m   <<<9, 256>>>(ipw);                  // launch 3
    k_conv<<<512, 256, SMEM_BYTES>>>(x, conv_w);  // launch 4  (ncu captures this)
    k_post<<<32, 256>>>(conv_b, ln_w, ln_b);  // launch 5
    k_fin <<<1, 256>>>(ipb, opb, out);        // launch 6

    (void)in_sizes; (void)n_in; (void)out_size;
}

// round 8
// speedup vs baseline: 1.0512x; 1.0512x over previous
#include <cuda_runtime.h>
#include <math.h>
#include <stddef.h>
#include <stdint.h>

// Problem constants: Dur=32, Dim=256, T=528
#define TT 528
#define NQB 12          // q-partial blocks for k_m (44 q each)

// Scratch (device globals: allocation-free)
__device__ float g_ypart[2][256 * TT];  // conv partial sums, layout [t][o]
__device__ float g_u[TT];
__device__ float g_a[4 * TT];           // a_w[q] = col-sums of opw rows 128w..
__device__ float g_mpart[NQB][4][TT];   // partial m_w[t] per q-block

// k_conv shared: xs1/xs2 transposed x copies + NBUF weight buffers
#define XR 34
#define XS1_FLOATS (128 * XR)
#define XS_TOTAL (2 * XS1_FLOATS)
#define WS_MAX_BYTES 73728
#define SMEM_BYTES (XS_TOTAL * 4 + WS_MAX_BYTES)

__device__ __forceinline__ uint32_t smem_u32(const void* p) {
    return (uint32_t)__cvta_generic_to_shared(p);
}
__device__ __forceinline__ unsigned long long pk2(float lo, float hi) {
    unsigned long long r;
    asm("mov.b64 %0, {%1, %2};" : "=l"(r) : "f"(lo), "f"(hi));
    return r;
}
__device__ __forceinline__ void upk2(float& lo, float& hi, unsigned long long v) {
    asm("mov.b64 {%0, %1}, %2;" : "=f"(lo), "=f"(hi) : "l"(v));
}
__device__ __forceinline__ void fma2(unsigned long long& d,
                                     unsigned long long a, unsigned long long b) {
    asm("fma.rn.f32x2 %0, %1, %2, %0;" : "+l"(d) : "l"(a), "l"(b));
}

// ---------------------------------------------------------------------------
// Stage 1: per-branch conv, templated on (K, L), f32x2 over t-pairs.
// ---------------------------------------------------------------------------
template<int K, int L>
__device__ __forceinline__ void conv_branch(
    const float* __restrict__ wB,
    const float* __restrict__ xs1, const float* __restrict__ xs2,
    float* __restrict__ ws,
    int otile, int ihalf, int tid,
    float* __restrict__ yout)
{
    constexpr int C4 = (K + 3) / 4;
    constexpr int SP = C4 * 4 + ((C4 & 1) ? 8 : 4);
    constexpr int NBUF = (K <= 8) ? 4 : ((K <= 16) ? 3 : 2);
    constexpr int BUF = 256 * SP;
    constexpr int L2 = L / 2;

    const int g = tid & 7;
    const int o = otile * 32 + (tid >> 3);

    unsigned long long acc2[L2 > 0 ? L2 : 1];
#pragma unroll
    for (int t = 0; t < L2; t++) acc2[t] = 0ull;
    float accT = 0.0f;

    auto stage = [&](int ii) {
        const int ibase = ihalf * 128 + ii * 8;
        const uint32_t wsb = smem_u32(ws + (ii % NBUF) * BUF);
#pragma unroll
        for (int k = 0; k < C4; k++) {
            int idx = tid + 256 * k;
            int r = idx / C4;
            int c = idx - r * C4;
            const float* src = wB + (size_t)(otile * 32 + (r >> 3)) * 8192
                                  + (size_t)(ibase + (r & 7)) * 32 + c * 4;
            asm volatile("cp.async.cg.shared.global [%0], [%1], 16;"
                         :: "r"(wsb + (uint32_t)(r * SP + c * 4) * 4), "l"(src));
        }
        asm volatile("cp.async.commit_group;");
    };

#pragma unroll
    for (int p = 0; p < NBUF - 1; p++) stage(p);

    for (int ii = 0; ii < 16; ++ii) {
        if (ii <= 16 - NBUF + 1) {
            asm volatile("cp.async.wait_group %0;" :: "n"(NBUF - 2));
        } else {
            asm volatile("cp.async.wait_group 0;");
        }
        __syncthreads();
        if (ii + NBUF - 1 < 16) stage(ii + NBUF - 1);

        const int il = ii * 8 + g;
        const float* x1r = xs1 + il * XR;
        const float* x2r = xs2 + il * XR;

        const float* wrow = ws + (ii % NBUF) * BUF + tid * SP;
        float wv[C4 * 4];
#pragma unroll
        for (int c = 0; c < C4; c++) {
            float4 w4 = *reinterpret_cast<const float4*>(wrow + c * 4);
            wv[c * 4 + 0] = w4.x; wv[c * 4 + 1] = w4.y;
            wv[c * 4 + 2] = w4.z; wv[c * 4 + 3] = w4.w;
        }
        unsigned long long ww[K > 1 ? K : 1];
        if constexpr (L2 > 0) {
#pragma unroll
            for (int h = 0; h < K; h++) ww[h] = pk2(wv[h], wv[h]);
        }

#pragma unroll
        for (int tp = 0; tp < L2; tp++) {
#pragma unroll
            for (int h = 0; h < K; h++) {
                unsigned long long xv = (h & 1)
                    ? *reinterpret_cast<const unsigned long long*>(x2r + 2 * (tp + (h - 1) / 2))
                    : *reinterpret_cast<const unsigned long long*>(x1r + 2 * (tp + h / 2));
                fma2(acc2[tp], xv, ww[h]);
            }
        }
        if constexpr (L & 1) {
#pragma unroll
            for (int h = 0; h < K; h++)
                accT = fmaf(x1r[L - 1 + h], wv[h], accT);
        }
        __syncwarp();
    }

#pragma unroll
    for (int tp = 0; tp < L2; tp++) {
        float a0, a1;
        upk2(a0, a1, acc2[tp]);
#pragma unroll
        for (int m = 1; m <= 4; m <<= 1) {
            a0 += __shfl_xor_sync(0xffffffffu, a0, m);
            a1 += __shfl_xor_sync(0xffffffffu, a1, m);
        }
        if (g == 0) {
            yout[(2 * tp) * 256 + o] = a0;
            yout[(2 * tp + 1) * 256 + o] = a1;
        }
    }
    if constexpr (L & 1) {
#pragma unroll
        for (int m = 1; m <= 4; m <<= 1)
            accT += __shfl_xor_sync(0xffffffffu, accT, m);
        if (g == 0) yout[(L - 1) * 256 + o] = accT;
    }
}

template<int B>
__device__ __forceinline__ void dispatch_branch(
    int b, const float* __restrict__ cw,
    const float* __restrict__ xs1, const float* __restrict__ xs2,
    float* __restrict__ ws, int otile, int ihalf, int tid)
{
    if (b == B) {
        constexpr int TOFF = B * 32 - (B * (B - 1)) / 2;
        conv_branch<B + 1, 32 - B>(cw + (size_t)B * (256 * 256 * 32),
                                   xs1, xs2, ws, otile, ihalf, tid,
                                   &g_ypart[ihalf][TOFF * 256]);
    } else if constexpr (B < 31) {
        dispatch_branch<B + 1>(b, cw, xs1, xs2, ws, otile, ihalf, tid);
    }
}

__global__ void __launch_bounds__(256) k_conv(
    const float* __restrict__ x, const float* __restrict__ cw)
{
    extern __shared__ float smem[];
    float* xs1 = smem;
    float* xs2 = smem + XS1_FLOATS;
    float* ws  = smem + XS_TOTAL;

    const int tid = threadIdx.x;
    const int ko = blockIdx.x >> 4;
    // complementary pairing, DRAM-longest first: 31,0,30,1,...,16,15
    const int b = (ko & 1) ? (ko >> 1) : (31 - (ko >> 1));
    const int sub = blockIdx.x & 15;
    const int otile = sub >> 1;
    const int ihalf = sub & 1;

    for (int idx = tid; idx < 4096; idx += 256) {
        int j = idx >> 7;
        int il = idx & 127;
        float v = x[j * 256 + ihalf * 128 + il];
        xs1[il * XR + j] = v;
        if (j > 0) xs2[il * XR + (j - 1)] = v;
    }
    __syncthreads();

    dispatch_branch<0>(b, cw, xs1, xs2, ws, otile, ihalf, tid);
}

// ---------------------------------------------------------------------------
// Stage 2 (fused): per-branch bias + exact gelu + mean/var + ln + channel-sum.
// ---------------------------------------------------------------------------
__global__ void __launch_bounds__(256) k_post(
    const float* __restrict__ conv_b,
    const float* __restrict__ lnw, const float* __restrict__ lnb)
{
    const int b = blockIdx.x;
    const int tid = threadIdx.x;
    const int L = 32 - b;
    const int toff = b * 32 - (b * (b - 1)) / 2;
    const int o = tid;

    const float* p0 = &g_ypart[0][toff * 256 + o];
    const float* p1 = &g_ypart[1][toff * 256 + o];
    const float cb = conv_b[b * 256 + o];

    float v[32];
    float s = 0.0f, s2 = 0.0f;
#pragma unroll
    for (int t = 0; t < 32; t++) {
        if (t < L) {
            float val = p0[t * 256] + p1[t * 256] + cb;
            float ge = 0.5f * val * (1.0f + erff(val * 0.70710678118654752440f));
            v[t] = ge;
            s += ge;
            s2 += ge * ge;
        }
    }

    __shared__ float sh[256];
    __shared__ float sh2[256];
    sh[tid] = s; sh2[tid] = s2;
    __syncthreads();
    for (int st = 128; st > 0; st >>= 1) {
        if (tid < st) { sh[tid] += sh[tid + st]; sh2[tid] += sh2[tid + st]; }
        __syncthreads();
    }
    __shared__ float s_mu, s_rs;
    if (tid == 0) {
        float inv = 1.0f / (float)(256 * L);
        float mu = sh[0] * inv;
        float var = sh2[0] * inv - mu * mu;
        s_mu = mu;
        s_rs = rsqrtf(var + 1e-5f);
    }
    __syncthreads();
    const float mu = s_mu, rs = s_rs;

    const float* lwp = lnw + ((size_t)b * 256 + o) * 32;
    const float* lbp = lnb + ((size_t)b * 256 + o) * 32;
    const int warp = tid >> 5, lane = tid & 31;
    __shared__ float red[32][9];

#pragma unroll
    for (int t = 0; t < 32; t++) {
        float c = 0.0f;
        if (t < L) c = fmaf((v[t] - mu) * rs, lwp[t], lbp[t]);
        c += __shfl_xor_sync(0xffffffffu, c, 16);
        c += __shfl_xor_sync(0xffffffffu, c, 8);
        c += __shfl_xor_sync(0xffffffffu, c, 4);
        c += __shfl_xor_sync(0xffffffffu, c, 2);
        c += __shfl_xor_sync(0xffffffffu, c, 1);
        if (lane == 0) red[t][warp] = c;
    }
    __syncthreads();
    if (tid < L) {
        float u = 0.0f;
#pragma unroll
        for (int w = 0; w < 8; w++) u += red[tid][w];
        g_u[toff + tid] = u;
    }
}

// ---------------------------------------------------------------------------
// k_a (input-only): a_w[q] = sum_{j<32} opw[128w+j, q].  part 0: w=0,1;
// part 1: w=2,3; grid 8 each (4 q-chunks of 132 per w).
// ---------------------------------------------------------------------------
__global__ void __launch_bounds__(132) k_a(const float* __restrict__ opw, int part)
{
    const int w = part * 2 + (blockIdx.x >> 2);
    const int chunk = blockIdx.x & 3;
    const int q = chunk * 132 + threadIdx.x;
    float a = 0.0f;
    const float* base = opw + (size_t)(128 * w) * TT + q;
#pragma unroll
    for (int j = 0; j < 32; j++) a += base[(size_t)j * TT];
    g_a[w * TT + q] = a;
}

// ---------------------------------------------------------------------------
// k_m (input-only): partial m_w[t] = sum_{q in block range} a_w[q]*ipw[2T+q, t]
// NQB blocks x 44 q-rows each; coalesced over t; covers t in THREE strips
// (tid, tid+256, tid+512) so the full TT=528 range is written.
// ---------------------------------------------------------------------------
__global__ void __launch_bounds__(256) k_m(const float* __restrict__ ipw)
{
    const int blk = blockIdx.x;
    const int tid = threadIdx.x;
    const int q0 = blk * 44;

    __shared__ float a_s[4][44];
    if (tid < 44 * 4) {
        int w = tid / 44, qq = tid % 44;
        a_s[w][qq] = g_a[w * TT + q0 + qq];
    }
    __syncthreads();

    const int t1 = tid;               // 0..255
    const int t2 = tid + 256;         // 256..511
    const int t3 = tid + 512;         // 512..527 (valid if tid < 16)
    float acc[4][3] = {};
    for (int qq = 0; qq < 44; qq++) {
        const float* row = ipw + (size_t)(2 * TT + q0 + qq) * TT;
        float v1 = row[t1];
        float v2 = row[t2];
        float v3 = (t3 < TT) ? row[t3] : 0.0f;
#pragma unroll
        for (int w = 0; w < 4; w++) {
            float aw = a_s[w][qq];
            acc[w][0] = fmaf(aw, v1, acc[w][0]);
            acc[w][1] = fmaf(aw, v2, acc[w][1]);
            acc[w][2] = fmaf(aw, v3, acc[w][2]);
        }
    }
#pragma unroll
    for (int w = 0; w < 4; w++) {
        g_mpart[blk][w][t1] = acc[w][0];
        g_mpart[blk][w][t2] = acc[w][1];
        if (t3 < TT) g_mpart[blk][w][t3] = acc[w][2];
    }
}

// ---------------------------------------------------------------------------
// k_fin: out[0,w,d] = (1/32)*( sum_t u[t]*m_w[t]
//                              + 256*sum_t a_w[t]*ipb[2T+t]
//                              + 256*sum_{j<32} opb[128w+j] )
// ---------------------------------------------------------------------------
__global__ void __launch_bounds__(256) k_fin(
    const float* __restrict__ ipb, const float* __restrict__ opb,
    float* __restrict__ out)
{
    const int tid = threadIdx.x;
    __shared__ float sh[256];
    __shared__ float tot[4];
#pragma unroll
    for (int w = 0; w < 4; w++) {
        float p = 0.0f;
        for (int t = tid; t < TT; t += 256) {
            float m = 0.0f;
#pragma unroll
            for (int blk = 0; blk < NQB; blk++) m += g_mpart[blk][w][t];
            p += g_u[t] * m + 256.0f * g_a[w * TT + t] * ipb[2 * TT + t];
        }
        if (tid < 32) p += 256.0f * opb[128 * w + tid];
        sh[tid] = p;
        __syncthreads();
        for (int st = 128; st > 0; st >>= 1) {
            if (tid < st) sh[tid] += sh[tid + st];
            __syncthreads();
        }
        if (tid == 0) tot[w] = sh[0] * (1.0f / 32.0f);
        __syncthreads();
    }
#pragma unroll
    for (int w = 0; w < 4; w++) out[w * 256 + tid] = tot[w];
}

// ---------------------------------------------------------------------------
extern "C" void kernel_launch(void* const* d_in, const int* in_sizes, int n_in,
                              void* d_out, int out_size)
{
    const float* x      = (const float*)d_in[0];
    const float* conv_w = (const float*)d_in[1];
    const float* conv_b = (const float*)d_in[2];
    const float* ln_w   = (const float*)d_in[3];
    const float* ln_b   = (const float*)d_in[4];
    const float* ipw    = (const float*)d_in[5];
    const float* ipb    = (const float*)d_in[6];
    const float* opw    = (const float*)d_in[7];
    const float* opb    = (const float*)d_in[8];
    float* out = (float*)d_out;

    cudaFuncSetAttribute(k_conv, cudaFuncAttributeMaxDynamicSharedMemorySize,
                         SMEM_BYTES);

    k_a   <<<8, 132>>>(opw, 0);                   // launch 1
    k_a   <<<8, 132>>>(opw, 1);                   // launch 2
    k_m   <<<NQB, 256>>>(ipw);                    // launch 3
    k_conv<<<512, 256, SMEM_BYTES>>>(x, conv_w);  // launch 4 (ncu captures this)
    k_post<<<32, 256>>>(conv_b, ln_w, ln_b);      // launch 5
    k_fin <<<1, 256>>>(ipb, opb, out);            // launch 6

    (void)in_sizes; (void)n_in; (void)out_size;
}

// round 9
// speedup vs baseline: 1.2733x; 1.2112x over previous
#include <cuda_runtime.h>
#include <math.h>
#include <stddef.h>
#include <stdint.h>

// Problem constants: Dur=32, Dim=256, T=528
#define TT 528
#define NQB 24          // q-partial blocks for k_m (22 q each)
#define QPB 22

// Scratch (device globals: allocation-free)
__device__ float g_ypart[2][256 * TT];  // conv partial sums, layout [t][o]
__device__ float g_mpart[NQB][4][TT];   // partial m_w[t] per q-block
__device__ float g_ipbdot[NQB][4];      // partial sum_q a_w[q]*ipb[2T+q]
__device__ float g_pdot[32][4];         // per-branch partial sum_t u[t]*m_w[t]

// k_conv shared: xs1/xs2 transposed x copies + NBUF weight buffers
#define XR 34
#define XS1_FLOATS (128 * XR)
#define XS_TOTAL (2 * XS1_FLOATS)
#define WS_MAX_BYTES 73728
#define SMEM_BYTES (XS_TOTAL * 4 + WS_MAX_BYTES)

__device__ __forceinline__ uint32_t smem_u32(const void* p) {
    return (uint32_t)__cvta_generic_to_shared(p);
}
__device__ __forceinline__ unsigned long long pk2(float lo, float hi) {
    unsigned long long r;
    asm("mov.b64 %0, {%1, %2};" : "=l"(r) : "f"(lo), "f"(hi));
    return r;
}
__device__ __forceinline__ void upk2(float& lo, float& hi, unsigned long long v) {
    asm("mov.b64 {%0, %1}, %2;" : "=f"(lo), "=f"(hi) : "l"(v));
}
__device__ __forceinline__ void fma2(unsigned long long& d,
                                     unsigned long long a, unsigned long long b) {
    asm("fma.rn.f32x2 %0, %1, %2, %0;" : "+l"(d) : "l"(a), "l"(b));
}

// ---------------------------------------------------------------------------
// Stage 1: per-branch conv, templated on (K, L), f32x2 over t-pairs.
// (identical internals to the measured-best R5 configuration)
// ---------------------------------------------------------------------------
template<int K, int L>
__device__ __forceinline__ void conv_branch(
    const float* __restrict__ wB,
    const float* __restrict__ xs1, const float* __restrict__ xs2,
    float* __restrict__ ws,
    int otile, int ihalf, int tid,
    float* __restrict__ yout)
{
    constexpr int C4 = (K + 3) / 4;
    constexpr int SP = C4 * 4 + ((C4 & 1) ? 8 : 4);
    constexpr int NBUF = (K <= 8) ? 4 : ((K <= 16) ? 3 : 2);
    constexpr int BUF = 256 * SP;
    constexpr int L2 = L / 2;

    const int g = tid & 7;
    const int o = otile * 32 + (tid >> 3);

    unsigned long long acc2[L2 > 0 ? L2 : 1];
#pragma unroll
    for (int t = 0; t < L2; t++) acc2[t] = 0ull;
    float accT = 0.0f;

    auto stage = [&](int ii) {
        const int ibase = ihalf * 128 + ii * 8;
        const uint32_t wsb = smem_u32(ws + (ii % NBUF) * BUF);
#pragma unroll
        for (int k = 0; k < C4; k++) {
            int idx = tid + 256 * k;
            int r = idx / C4;
            int c = idx - r * C4;
            const float* src = wB + (size_t)(otile * 32 + (r >> 3)) * 8192
                                  + (size_t)(ibase + (r & 7)) * 32 + c * 4;
            asm volatile("cp.async.cg.shared.global [%0], [%1], 16;"
                         :: "r"(wsb + (uint32_t)(r * SP + c * 4) * 4), "l"(src));
        }
        asm volatile("cp.async.commit_group;");
    };

#pragma unroll
    for (int p = 0; p < NBUF - 1; p++) stage(p);

    for (int ii = 0; ii < 16; ++ii) {
        if (ii <= 16 - NBUF + 1) {
            asm volatile("cp.async.wait_group %0;" :: "n"(NBUF - 2));
        } else {
            asm volatile("cp.async.wait_group 0;");
        }
        __syncthreads();
        if (ii + NBUF - 1 < 16) stage(ii + NBUF - 1);

        const int il = ii * 8 + g;
        const float* x1r = xs1 + il * XR;
        const float* x2r = xs2 + il * XR;

        const float* wrow = ws + (ii % NBUF) * BUF + tid * SP;
        float wv[C4 * 4];
#pragma unroll
        for (int c = 0; c < C4; c++) {
            float4 w4 = *reinterpret_cast<const float4*>(wrow + c * 4);
            wv[c * 4 + 0] = w4.x; wv[c * 4 + 1] = w4.y;
            wv[c * 4 + 2] = w4.z; wv[c * 4 + 3] = w4.w;
        }
        unsigned long long ww[K > 1 ? K : 1];
        if constexpr (L2 > 0) {
#pragma unroll
            for (int h = 0; h < K; h++) ww[h] = pk2(wv[h], wv[h]);
        }

#pragma unroll
        for (int tp = 0; tp < L2; tp++) {
#pragma unroll
            for (int h = 0; h < K; h++) {
                unsigned long long xv = (h & 1)
                    ? *reinterpret_cast<const unsigned long long*>(x2r + 2 * (tp + (h - 1) / 2))
                    : *reinterpret_cast<const unsigned long long*>(x1r + 2 * (tp + h / 2));
                fma2(acc2[tp], xv, ww[h]);
            }
        }
        if constexpr (L & 1) {
#pragma unroll
            for (int h = 0; h < K; h++)
                accT = fmaf(x1r[L - 1 + h], wv[h], accT);
        }
        __syncwarp();
    }

#pragma unroll
    for (int tp = 0; tp < L2; tp++) {
        float a0, a1;
        upk2(a0, a1, acc2[tp]);
#pragma unroll
        for (int m = 1; m <= 4; m <<= 1) {
            a0 += __shfl_xor_sync(0xffffffffu, a0, m);
            a1 += __shfl_xor_sync(0xffffffffu, a1, m);
        }
        if (g == 0) {
            yout[(2 * tp) * 256 + o] = a0;
            yout[(2 * tp + 1) * 256 + o] = a1;
        }
    }
    if constexpr (L & 1) {
#pragma unroll
        for (int m = 1; m <= 4; m <<= 1)
            accT += __shfl_xor_sync(0xffffffffu, accT, m);
        if (g == 0) yout[(L - 1) * 256 + o] = accT;
    }
}

template<int B>
__device__ __forceinline__ void dispatch_branch(
    int b, const float* __restrict__ cw,
    const float* __restrict__ xs1, const float* __restrict__ xs2,
    float* __restrict__ ws, int otile, int ihalf, int tid)
{
    if (b == B) {
        constexpr int TOFF = B * 32 - (B * (B - 1)) / 2;
        conv_branch<B + 1, 32 - B>(cw + (size_t)B * (256 * 256 * 32),
                                   xs1, xs2, ws, otile, ihalf, tid,
                                   &g_ypart[ihalf][TOFF * 256]);
    } else if constexpr (B < 31) {
        dispatch_branch<B + 1>(b, cw, xs1, xs2, ws, otile, ihalf, tid);
    }
}

__global__ void __launch_bounds__(256) k_conv(
    const float* __restrict__ x, const float* __restrict__ cw)
{
    extern __shared__ float smem[];
    float* xs1 = smem;
    float* xs2 = smem + XS1_FLOATS;
    float* ws  = smem + XS_TOTAL;

    const int tid = threadIdx.x;
    const int ko = blockIdx.x >> 4;
    // heavy-first (measured best): 16,15,17,14,...  (K*L max at b=15,16)
    const int b = (ko & 1) ? (16 + (ko >> 1)) : (15 - (ko >> 1));
    const int sub = blockIdx.x & 15;
    const int otile = sub >> 1;
    const int ihalf = sub & 1;

    for (int idx = tid; idx < 4096; idx += 256) {
        int j = idx >> 7;
        int il = idx & 127;
        float v = x[j * 256 + ihalf * 128 + il];
        xs1[il * XR + j] = v;
        if (j > 0) xs2[il * XR + (j - 1)] = v;
    }
    __syncthreads();

    dispatch_branch<0>(b, cw, xs1, xs2, ws, otile, ihalf, tid);
}

// ---------------------------------------------------------------------------
// k_m (input-only, fuses a-slice + m-partial + ipb-dot-partial).
// Block `blk` handles q in [blk*QPB, blk*QPB+QPB).
//   a_w[q]           = sum_{j<32} opw[128w+j, q]            (computed in-block)
//   m_w[t] partial   = sum_q a_w[q] * ipw[2T+q, t]
//   ipbdot_w partial = sum_q a_w[q] * ipb[2T+q]
// ---------------------------------------------------------------------------
__global__ void __launch_bounds__(256) k_m(
    const float* __restrict__ opw, const float* __restrict__ ipw,
    const float* __restrict__ ipb, int part)
{
    const int blk = part * 12 + blockIdx.x;
    const int tid = threadIdx.x;
    const int q0 = blk * QPB;

    __shared__ float a_s[4][QPB];
    if (tid < 4 * QPB) {
        int w = tid / QPB, qq = tid - w * QPB;
        float a = 0.0f;
        const float* base = opw + (size_t)(128 * w) * TT + (q0 + qq);
#pragma unroll
        for (int j = 0; j < 32; j++) a += base[(size_t)j * TT];
        a_s[w][qq] = a;
    }
    __syncthreads();

    const int t1 = tid;               // 0..255
    const int t2 = tid + 256;         // 256..511
    const int t3 = tid + 512;         // 512..527 (valid if tid < 16)
    float acc[4][3] = {};
    for (int qq = 0; qq < QPB; qq++) {
        const float* row = ipw + (size_t)(2 * TT + q0 + qq) * TT;
        float v1 = row[t1];
        float v2 = row[t2];
        float v3 = (t3 < TT) ? row[t3] : 0.0f;
#pragma unroll
        for (int w = 0; w < 4; w++) {
            float aw = a_s[w][qq];
            acc[w][0] = fmaf(aw, v1, acc[w][0]);
            acc[w][1] = fmaf(aw, v2, acc[w][1]);
            acc[w][2] = fmaf(aw, v3, acc[w][2]);
        }
    }
#pragma unroll
    for (int w = 0; w < 4; w++) {
        g_mpart[blk][w][t1] = acc[w][0];
        g_mpart[blk][w][t2] = acc[w][1];
        if (t3 < TT) g_mpart[blk][w][t3] = acc[w][2];
    }
    if (tid < 4) {
        const int w = tid;
        float d = 0.0f;
        for (int qq = 0; qq < QPB; qq++)
            d += a_s[w][qq] * ipb[2 * TT + q0 + qq];
        g_ipbdot[blk][w] = d;
    }
}

// ---------------------------------------------------------------------------
// Stage 2 (fused): bias + exact gelu + mean/var + ln + channel-sum -> u[t],
// then immediately the per-branch partial out-dot  sum_t u[t]*m_w[t].
// ---------------------------------------------------------------------------
__global__ void __launch_bounds__(256) k_post(
    const float* __restrict__ conv_b,
    const float* __restrict__ lnw, const float* __restrict__ lnb)
{
    const int b = blockIdx.x;
    const int tid = threadIdx.x;
    const int L = 32 - b;
    const int toff = b * 32 - (b * (b - 1)) / 2;
    const int o = tid;

    const float* p0 = &g_ypart[0][toff * 256 + o];
    const float* p1 = &g_ypart[1][toff * 256 + o];
    const float cb = conv_b[b * 256 + o];

    float v[32];
    float s = 0.0f, s2 = 0.0f;
#pragma unroll
    for (int t = 0; t < 32; t++) {
        if (t < L) {
            float val = p0[t * 256] + p1[t * 256] + cb;
            float ge = 0.5f * val * (1.0f + erff(val * 0.70710678118654752440f));
            v[t] = ge;
            s += ge;
            s2 += ge * ge;
        }
    }

    __shared__ float sh[256];
    __shared__ float sh2[256];
    sh[tid] = s; sh2[tid] = s2;
    __syncthreads();
    for (int st = 128; st > 0; st >>= 1) {
        if (tid < st) { sh[tid] += sh[tid + st]; sh2[tid] += sh2[tid + st]; }
        __syncthreads();
    }
    __shared__ float s_mu, s_rs;
    if (tid == 0) {
        float inv = 1.0f / (float)(256 * L);
        float mu = sh[0] * inv;
        float var = sh2[0] * inv - mu * mu;
        s_mu = mu;
        s_rs = rsqrtf(var + 1e-5f);
    }
    __syncthreads();
    const float mu = s_mu, rs = s_rs;

    const float* lwp = lnw + ((size_t)b * 256 + o) * 32;
    const float* lbp = lnb + ((size_t)b * 256 + o) * 32;
    const int warp = tid >> 5, lane = tid & 31;
    __shared__ float red[32][9];

#pragma unroll
    for (int t = 0; t < 32; t++) {
        float c = 0.0f;
        if (t < L) c = fmaf((v[t] - mu) * rs, lwp[t], lbp[t]);
        c += __shfl_xor_sync(0xffffffffu, c, 16);
        c += __shfl_xor_sync(0xffffffffu, c, 8);
        c += __shfl_xor_sync(0xffffffffu, c, 4);
        c += __shfl_xor_sync(0xffffffffu, c, 2);
        c += __shfl_xor_sync(0xffffffffu, c, 1);
        if (lane == 0) red[t][warp] = c;
    }
    __syncthreads();

    // warp 0: u[t] for t = toff+tid (tid < L), then partial out-dot per w
    if (warp == 0) {
        float u = 0.0f;
        if (lane < L) {
#pragma unroll
            for (int w8 = 0; w8 < 8; w8++) u += red[lane][w8];
        }
        const int t = toff + lane;
#pragma unroll
        for (int w = 0; w < 4; w++) {
            float m = 0.0f;
            if (lane < L) {
#pragma unroll
                for (int blk = 0; blk < NQB; blk++) m += g_mpart[blk][w][t];
            }
            float pd = u * m;
            pd += __shfl_xor_sync(0xffffffffu, pd, 16);
            pd += __shfl_xor_sync(0xffffffffu, pd, 8);
            pd += __shfl_xor_sync(0xffffffffu, pd, 4);
            pd += __shfl_xor_sync(0xffffffffu, pd, 2);
            pd += __shfl_xor_sync(0xffffffffu, pd, 1);
            if (lane == 0) g_pdot[b][w] = pd;
        }
    }
}

// ---------------------------------------------------------------------------
// k_fin (micro): out[0,w,d] = (1/32)*( sum_b pdot[b][w]
//                 + 256*sum_blk ipbdot[blk][w] + 256*sum_{j<32} opb[128w+j] )
// ---------------------------------------------------------------------------
__global__ void __launch_bounds__(128) k_fin(
    const float* __restrict__ opb, float* __restrict__ out)
{
    const int tid = threadIdx.x;
    const int w = tid >> 5, lane = tid & 31;
    __shared__ float tot[4];

    float v = g_pdot[lane][w];
    if (lane < NQB) v += 256.0f * g_ipbdot[lane][w];
    v += 256.0f * opb[128 * w + lane];
    v += __shfl_xor_sync(0xffffffffu, v, 16);
    v += __shfl_xor_sync(0xffffffffu, v, 8);
    v += __shfl_xor_sync(0xffffffffu, v, 4);
    v += __shfl_xor_sync(0xffffffffu, v, 2);
    v += __shfl_xor_sync(0xffffffffu, v, 1);
    if (lane == 0) tot[w] = v * (1.0f / 32.0f);
    __syncthreads();

    for (int idx = tid; idx < 1024; idx += 128) out[idx] = tot[idx >> 8];
}

// ---------------------------------------------------------------------------
extern "C" void kernel_launch(void* const* d_in, const int* in_sizes, int n_in,
                              void* d_out, int out_size)
{
    const float* x      = (const float*)d_in[0];
    const float* conv_w = (const float*)d_in[1];
    const float* conv_b = (const float*)d_in[2];
    const float* ln_w   = (const float*)d_in[3];
    const float* ln_b   = (const float*)d_in[4];
    const float* ipw    = (const float*)d_in[5];
    const float* ipb    = (const float*)d_in[6];
    const float* opw    = (const float*)d_in[7];
    const float* opb    = (const float*)d_in[8];
    float* out = (float*)d_out;

    cudaFuncSetAttribute(k_conv, cudaFuncAttributeMaxDynamicSharedMemorySize,
                         SMEM_BYTES);

    k_m   <<<12, 256>>>(opw, ipw, ipb, 0);        // launch 1
    k_m   <<<12, 256>>>(opw, ipw, ipb, 1);        // launch 2
    k_conv<<<512, 256, SMEM_BYTES>>>(x, conv_w);  // launch 3
    k_post<<<32, 256>>>(conv_b, ln_w, ln_b);      // launch 4 (ncu captures this)
    k_fin <<<1, 128>>>(opb, out);                 // launch 5

    (void)in_sizes; (void)n_in; (void)out_size;
}

// round 10
// speedup vs baseline: 1.5526x; 1.2193x over previous
#include <cuda_runtime.h>
#include <math.h>
#include <stddef.h>
#include <stdint.h>

// Problem constants: Dur=32, Dim=256, T=528
#define TT 528
#define NQB 24          // q-partial blocks for m (22 q each)
#define QPB 22

// Scratch (device globals: allocation-free)
__device__ float g_ypart[2][256 * TT];  // conv partial sums, layout [t][o]
__device__ float g_mpart[NQB][4][TT];   // partial m_w[t] per q-block
__device__ float g_ipbdot[NQB][4];      // partial sum_q a_w[q]*ipb[2T+q]
__device__ float g_pdot[32][4];         // per-branch partial sum_t u[t]*m_w[t]
__device__ int   g_cnt;                 // completion counter (self-resetting)

// k_conv shared: xs1/xs2 transposed x copies + NBUF weight buffers
#define XR 34
#define XS1_FLOATS (128 * XR)
#define XS_TOTAL (2 * XS1_FLOATS)
#define WS_MAX_BYTES 73728
#define SMEM_BYTES (XS_TOTAL * 4 + WS_MAX_BYTES)

__device__ __forceinline__ uint32_t smem_u32(const void* p) {
    return (uint32_t)__cvta_generic_to_shared(p);
}
__device__ __forceinline__ unsigned long long pk2(float lo, float hi) {
    unsigned long long r;
    asm("mov.b64 %0, {%1, %2};" : "=l"(r) : "f"(lo), "f"(hi));
    return r;
}
__device__ __forceinline__ void upk2(float& lo, float& hi, unsigned long long v) {
    asm("mov.b64 {%0, %1}, %2;" : "=f"(lo), "=f"(hi) : "l"(v));
}
__device__ __forceinline__ void fma2(unsigned long long& d,
                                     unsigned long long a, unsigned long long b) {
    asm("fma.rn.f32x2 %0, %1, %2, %0;" : "+l"(d) : "l"(a), "l"(b));
}

// ---------------------------------------------------------------------------
// Conv branch, templated on (K, L), f32x2 over t-pairs (R5 measured-best).
// ---------------------------------------------------------------------------
template<int K, int L>
__device__ __forceinline__ void conv_branch(
    const float* __restrict__ wB,
    const float* __restrict__ xs1, const float* __restrict__ xs2,
    float* __restrict__ ws,
    int otile, int ihalf, int tid,
    float* __restrict__ yout)
{
    constexpr int C4 = (K + 3) / 4;
    constexpr int SP = C4 * 4 + ((C4 & 1) ? 8 : 4);
    constexpr int NBUF = (K <= 8) ? 4 : ((K <= 16) ? 3 : 2);
    constexpr int BUF = 256 * SP;
    constexpr int L2 = L / 2;

    const int g = tid & 7;
    const int o = otile * 32 + (tid >> 3);

    unsigned long long acc2[L2 > 0 ? L2 : 1];
#pragma unroll
    for (int t = 0; t < L2; t++) acc2[t] = 0ull;
    float accT = 0.0f;

    auto stage = [&](int ii) {
        const int ibase = ihalf * 128 + ii * 8;
        const uint32_t wsb = smem_u32(ws + (ii % NBUF) * BUF);
#pragma unroll
        for (int k = 0; k < C4; k++) {
            int idx = tid + 256 * k;
            int r = idx / C4;
            int c = idx - r * C4;
            const float* src = wB + (size_t)(otile * 32 + (r >> 3)) * 8192
                                  + (size_t)(ibase + (r & 7)) * 32 + c * 4;
            asm volatile("cp.async.cg.shared.global [%0], [%1], 16;"
                         :: "r"(wsb + (uint32_t)(r * SP + c * 4) * 4), "l"(src));
        }
        asm volatile("cp.async.commit_group;");
    };

#pragma unroll
    for (int p = 0; p < NBUF - 1; p++) stage(p);

    for (int ii = 0; ii < 16; ++ii) {
        if (ii <= 16 - NBUF + 1) {
            asm volatile("cp.async.wait_group %0;" :: "n"(NBUF - 2));
        } else {
            asm volatile("cp.async.wait_group 0;");
        }
        __syncthreads();
        if (ii + NBUF - 1 < 16) stage(ii + NBUF - 1);

        const int il = ii * 8 + g;
        const float* x1r = xs1 + il * XR;
        const float* x2r = xs2 + il * XR;

        const float* wrow = ws + (ii % NBUF) * BUF + tid * SP;
        float wv[C4 * 4];
#pragma unroll
        for (int c = 0; c < C4; c++) {
            float4 w4 = *reinterpret_cast<const float4*>(wrow + c * 4);
            wv[c * 4 + 0] = w4.x; wv[c * 4 + 1] = w4.y;
            wv[c * 4 + 2] = w4.z; wv[c * 4 + 3] = w4.w;
        }
        unsigned long long ww[K > 1 ? K : 1];
        if constexpr (L2 > 0) {
#pragma unroll
            for (int h = 0; h < K; h++) ww[h] = pk2(wv[h], wv[h]);
        }

#pragma unroll
        for (int tp = 0; tp < L2; tp++) {
#pragma unroll
            for (int h = 0; h < K; h++) {
                unsigned long long xv = (h & 1)
                    ? *reinterpret_cast<const unsigned long long*>(x2r + 2 * (tp + (h - 1) / 2))
                    : *reinterpret_cast<const unsigned long long*>(x1r + 2 * (tp + h / 2));
                fma2(acc2[tp], xv, ww[h]);
            }
        }
        if constexpr (L & 1) {
#pragma unroll
            for (int h = 0; h < K; h++)
                accT = fmaf(x1r[L - 1 + h], wv[h], accT);
        }
        __syncwarp();
    }

#pragma unroll
    for (int tp = 0; tp < L2; tp++) {
        float a0, a1;
        upk2(a0, a1, acc2[tp]);
#pragma unroll
        for (int m = 1; m <= 4; m <<= 1) {
            a0 += __shfl_xor_sync(0xffffffffu, a0, m);
            a1 += __shfl_xor_sync(0xffffffffu, a1, m);
        }
        if (g == 0) {
            yout[(2 * tp) * 256 + o] = a0;
            yout[(2 * tp + 1) * 256 + o] = a1;
        }
    }
    if constexpr (L & 1) {
#pragma unroll
        for (int m = 1; m <= 4; m <<= 1)
            accT += __shfl_xor_sync(0xffffffffu, accT, m);
        if (g == 0) yout[(L - 1) * 256 + o] = accT;
    }
}

template<int B>
__device__ __forceinline__ void dispatch_branch(
    int b, const float* __restrict__ cw,
    const float* __restrict__ xs1, const float* __restrict__ xs2,
    float* __restrict__ ws, int otile, int ihalf, int tid)
{
    if (b == B) {
        constexpr int TOFF = B * 32 - (B * (B - 1)) / 2;
        conv_branch<B + 1, 32 - B>(cw + (size_t)B * (256 * 256 * 32),
                                   xs1, xs2, ws, otile, ihalf, tid,
                                   &g_ypart[ihalf][TOFF * 256]);
    } else if constexpr (B < 31) {
        dispatch_branch<B + 1>(b, cw, xs1, xs2, ws, otile, ihalf, tid);
    }
}

// ---------------------------------------------------------------------------
// m-partial role (input-only), absorbed into k_conv's grid (blocks 0..23):
//   a_w[q]           = sum_{j<32} opw[128w+j, q]
//   m_w[t] partial   = sum_q a_w[q] * ipw[2T+q, t]
//   ipbdot_w partial = sum_q a_w[q] * ipb[2T+q]
// ---------------------------------------------------------------------------
__device__ void m_role(
    const float* __restrict__ opw, const float* __restrict__ ipw,
    const float* __restrict__ ipb, int blk, int tid, float* __restrict__ a_sh)
{
    const int q0 = blk * QPB;
    float (*a_s)[QPB] = reinterpret_cast<float (*)[QPB]>(a_sh);

    if (tid < 4 * QPB) {
        int w = tid / QPB, qq = tid - w * QPB;
        float a = 0.0f;
        const float* base = opw + (size_t)(128 * w) * TT + (q0 + qq);
#pragma unroll
        for (int j = 0; j < 32; j++) a += base[(size_t)j * TT];
        a_s[w][qq] = a;
    }
    __syncthreads();

    const int t1 = tid;
    const int t2 = tid + 256;
    const int t3 = tid + 512;
    float acc[4][3] = {};
    for (int qq = 0; qq < QPB; qq++) {
        const float* row = ipw + (size_t)(2 * TT + q0 + qq) * TT;
        float v1 = row[t1];
        float v2 = row[t2];
        float v3 = (t3 < TT) ? row[t3] : 0.0f;
#pragma unroll
        for (int w = 0; w < 4; w++) {
            float aw = a_s[w][qq];
            acc[w][0] = fmaf(aw, v1, acc[w][0]);
            acc[w][1] = fmaf(aw, v2, acc[w][1]);
            acc[w][2] = fmaf(aw, v3, acc[w][2]);
        }
    }
#pragma unroll
    for (int w = 0; w < 4; w++) {
        g_mpart[blk][w][t1] = acc[w][0];
        g_mpart[blk][w][t2] = acc[w][1];
        if (t3 < TT) g_mpart[blk][w][t3] = acc[w][2];
    }
    if (tid < 4) {
        const int w = tid;
        float d = 0.0f;
        for (int qq = 0; qq < QPB; qq++)
            d += a_s[w][qq] * ipb[2 * TT + q0 + qq];
        g_ipbdot[blk][w] = d;
    }
}

__global__ void __launch_bounds__(256) k_conv(
    const float* __restrict__ x, const float* __restrict__ cw,
    const float* __restrict__ opw, const float* __restrict__ ipw,
    const float* __restrict__ ipb)
{
    extern __shared__ float smem[];
    const int tid = threadIdx.x;

    if (blockIdx.x < NQB) {           // m-partial role
        m_role(opw, ipw, ipb, blockIdx.x, tid, smem);
        return;
    }

    float* xs1 = smem;
    float* xs2 = smem + XS1_FLOATS;
    float* ws  = smem + XS_TOTAL;

    const int cb = blockIdx.x - NQB;  // 0..511
    const int ko = cb >> 4;
    // heavy-first (measured best): 16,15,17,14,...
    const int b = (ko & 1) ? (16 + (ko >> 1)) : (15 - (ko >> 1));
    const int sub = cb & 15;
    const int otile = sub >> 1;
    const int ihalf = sub & 1;

    for (int idx = tid; idx < 4096; idx += 256) {
        int j = idx >> 7;
        int il = idx & 127;
        float v = x[j * 256 + ihalf * 128 + il];
        xs1[il * XR + j] = v;
        if (j > 0) xs2[il * XR + (j - 1)] = v;
    }
    __syncthreads();

    dispatch_branch<0>(b, cw, xs1, xs2, ws, otile, ihalf, tid);
}

// ---------------------------------------------------------------------------
// k_post (1024 threads/block, 32 blocks = 1 per branch):
//   bias + exact gelu + mean/var + ln + channel-sum -> u[t]
//   -> per-branch pdot[b][w] = sum_t u[t]*m_w[t]
//   -> last block finishes: out = (1/32)(sum_b pdot + 256*ipbdot + 256*opb)
// thread = (tg, o): tg = tid>>8 handles t in [8tg, 8tg+8), o = tid&255.
// ---------------------------------------------------------------------------
__global__ void __launch_bounds__(1024) k_post(
    const float* __restrict__ conv_b,
    const float* __restrict__ lnw, const float* __restrict__ lnb,
    const float* __restrict__ opb, float* __restrict__ out)
{
    const int b = blockIdx.x;
    const int tid = threadIdx.x;
    const int L = 32 - b;
    const int toff = b * 32 - (b * (b - 1)) / 2;
    const int tg = tid >> 8;
    const int o = tid & 255;
    const int t0 = tg * 8;
    const int warpIdx = tid >> 5, lane = tid & 31;

    const float* p0 = &g_ypart[0][toff * 256 + o];
    const float* p1 = &g_ypart[1][toff * 256 + o];
    const float cbv = conv_b[b * 256 + o];

    float v[8];
    float s = 0.0f, s2 = 0.0f;
#pragma unroll
    for (int k = 0; k < 8; k++) {
        int t = t0 + k;
        if (t < L) {
            float val = p0[t * 256] + p1[t * 256] + cbv;
            float ge = 0.5f * val * (1.0f + erff(val * 0.70710678118654752440f));
            v[k] = ge;
            s += ge;
            s2 += ge * ge;
        }
    }

    // block reduce of s, s2 (warp shuffle + 32 partials)
    __shared__ float shs[32], shs2[32];
#pragma unroll
    for (int m = 16; m > 0; m >>= 1) {
        s  += __shfl_xor_sync(0xffffffffu, s, m);
        s2 += __shfl_xor_sync(0xffffffffu, s2, m);
    }
    if (lane == 0) { shs[warpIdx] = s; shs2[warpIdx] = s2; }
    __syncthreads();
    __shared__ float s_mu, s_rs;
    if (warpIdx == 0) {
        float a = shs[lane], a2 = shs2[lane];
#pragma unroll
        for (int m = 16; m > 0; m >>= 1) {
            a  += __shfl_xor_sync(0xffffffffu, a, m);
            a2 += __shfl_xor_sync(0xffffffffu, a2, m);
        }
        if (lane == 0) {
            float inv = 1.0f / (float)(256 * L);
            float mu = a * inv;
            float var = a2 * inv - mu * mu;
            s_mu = mu;
            s_rs = rsqrtf(var + 1e-5f);
        }
    }
    __syncthreads();
    const float mu = s_mu, rs = s_rs;

    // ln + channel partial sums: red[t][j], j = warpIdx & 7 (warps of this tg)
    const float* lwp = lnw + ((size_t)b * 256 + o) * 32;
    const float* lbp = lnb + ((size_t)b * 256 + o) * 32;
    __shared__ float red[32][9];
    const int j = warpIdx & 7;
#pragma unroll
    for (int k = 0; k < 8; k++) {
        int t = t0 + k;
        float c = 0.0f;
        if (t < L) c = fmaf((v[k] - mu) * rs, lwp[t], lbp[t]);
#pragma unroll
        for (int m = 16; m > 0; m >>= 1) c += __shfl_xor_sync(0xffffffffu, c, m);
        if (lane == 0 && t < L) red[t][j] = c;
    }
    __syncthreads();

    // warps 0..3: w = warpIdx; lane = t; u then pdot
    if (warpIdx < 4) {
        const int w = warpIdx;
        float u = 0.0f;
        if (lane < L) {
#pragma unroll
            for (int jj = 0; jj < 8; jj++) u += red[lane][jj];
        }
        float m = 0.0f;
        if (lane < L) {
            const int t = toff + lane;
#pragma unroll
            for (int blk = 0; blk < NQB; blk++) m += g_mpart[blk][w][t];
        }
        float pd = u * m;
#pragma unroll
        for (int mm = 16; mm > 0; mm >>= 1) pd += __shfl_xor_sync(0xffffffffu, pd, mm);
        if (lane == 0) g_pdot[b][w] = pd;
    }
    __threadfence();
    __syncthreads();

    // last-block finish
    __shared__ int s_last;
    if (tid == 0) s_last = (atomicAdd(&g_cnt, 1) == 31) ? 1 : 0;
    __syncthreads();
    if (s_last == 0) return;
    __threadfence();

    __shared__ float tot[4];
    if (tid < 128) {
        const int w = tid >> 5;
        const int l = tid & 31;
        float val = g_pdot[l][w];
        if (l < NQB) val += 256.0f * g_ipbdot[l][w];
        val += 256.0f * opb[128 * w + l];
#pragma unroll
        for (int m = 16; m > 0; m >>= 1) val += __shfl_xor_sync(0xffffffffu, val, m);
        if (l == 0) tot[w] = val * (1.0f / 32.0f);
    }
    __syncthreads();
    if (tid < 1024) out[tid] = tot[tid >> 8];
    if (tid == 0) g_cnt = 0;          // reset for next graph replay
}

// ---------------------------------------------------------------------------
extern "C" void kernel_launch(void* const* d_in, const int* in_sizes, int n_in,
                              void* d_out, int out_size)
{
    const float* x      = (const float*)d_in[0];
    const float* conv_w = (const float*)d_in[1];
    const float* conv_b = (const float*)d_in[2];
    const float* ln_w   = (const float*)d_in[3];
    const float* ln_b   = (const float*)d_in[4];
    const float* ipw    = (const float*)d_in[5];
    const float* ipb    = (const float*)d_in[6];
    const float* opw    = (const float*)d_in[7];
    const float* opb    = (const float*)d_in[8];
    float* out = (float*)d_out;

    cudaFuncSetAttribute(k_conv, cudaFuncAttributeMaxDynamicSharedMemorySize,
                         SMEM_BYTES);

    k_conv<<<512 + NQB, 256, SMEM_BYTES>>>(x, conv_w, opw, ipw, ipb);
    k_post<<<32, 1024>>>(conv_b, ln_w, ln_b, opb, out);

    (void)in_sizes; (void)n_in; (void)out_size;
}

// round 11
// speedup vs baseline: 1.6031x; 1.0326x over previous
#include <cuda_runtime.h>
#include <math.h>
#include <stddef.h>
#include <stdint.h>

// Problem constants: Dur=32, Dim=256, T=528
#define TT 528
#define NQB 24          // q-partial blocks for m (22 q each)
#define QPB 22

// Scratch (device globals: allocation-free)
// parts: 0,1 = ihalf{0,1} of taps 0..15 (or full K if K<=16); 2,3 = taps 16+
__device__ float g_ypart[4][256 * TT];
__device__ float g_mpart[NQB][4][TT];
__device__ float g_ipbdot[NQB][4];
__device__ float g_sp[32][8][2];        // per (branch, o-group) partial {s, s2}
__device__ float g_pdot2[128][4];       // per (branch*4+tg, w) partial u.m dot
__device__ int   g_cnt;                 // kB completion counter (self-reset)

// k_conv shared: xs1/xs2 transposed x copies + 2..3 weight buffers (SP<=20)
#define XR 34
#define XS1_FLOATS (128 * XR)
#define XS_TOTAL (2 * XS1_FLOATS)       // 8704 floats = 34816 B
#define WS_BYTES 40960                  // 2 x 256 x 20 x 4
#define SMEM_BYTES (XS_TOTAL * 4 + WS_BYTES)   // 75776 B -> 3 blocks/SM

__device__ __forceinline__ uint32_t smem_u32(const void* p) {
    return (uint32_t)__cvta_generic_to_shared(p);
}
__device__ __forceinline__ unsigned long long pk2(float lo, float hi) {
    unsigned long long r;
    asm("mov.b64 %0, {%1, %2};" : "=l"(r) : "f"(lo), "f"(hi));
    return r;
}
__device__ __forceinline__ void upk2(float& lo, float& hi, unsigned long long v) {
    asm("mov.b64 {%0, %1}, %2;" : "=f"(lo), "=f"(hi) : "l"(v));
}
__device__ __forceinline__ void fma2(unsigned long long& d,
                                     unsigned long long a, unsigned long long b) {
    asm("fma.rn.f32x2 %0, %1, %2, %0;" : "+l"(d) : "l"(a), "l"(b));
}

// ---------------------------------------------------------------------------
// Conv sub-branch: taps [KOFF, KOFF+K) of a branch with output length L.
// K <= 16 always (K-split). f32x2 over t-pairs; weights cp.async pipelined.
// ---------------------------------------------------------------------------
template<int K, int L, int KOFF>
__device__ __forceinline__ void conv_branch(
    const float* __restrict__ wB,
    const float* __restrict__ xs1, const float* __restrict__ xs2,
    float* __restrict__ ws,
    int otile, int ihalf, int tid,
    float* __restrict__ yout)
{
    constexpr int C4 = (K + 3) / 4;                  // <= 4
    constexpr int SP = C4 * 4 + ((C4 & 1) ? 8 : 4);  // 12 or 20, %8==4
    constexpr int NBUF = (C4 <= 2) ? 3 : 2;          // fits WS_BYTES
    constexpr int BUF = 256 * SP;
    constexpr int L2 = L / 2;

    const int g = tid & 7;
    const int o = otile * 32 + (tid >> 3);

    unsigned long long acc2[L2 > 0 ? L2 : 1];
#pragma unroll
    for (int t = 0; t < L2; t++) acc2[t] = 0ull;
    float accT = 0.0f;

    auto stage = [&](int ii) {
        const int ibase = ihalf * 128 + ii * 8;
        const uint32_t wsb = smem_u32(ws + (ii % NBUF) * BUF);
#pragma unroll
        for (int k = 0; k < C4; k++) {
            int idx = tid + 256 * k;
            int r = idx / C4;
            int c = idx - r * C4;
            const float* src = wB + (size_t)(otile * 32 + (r >> 3)) * 8192
                                  + (size_t)(ibase + (r & 7)) * 32 + KOFF + c * 4;
            asm volatile("cp.async.cg.shared.global [%0], [%1], 16;"
                         :: "r"(wsb + (uint32_t)(r * SP + c * 4) * 4), "l"(src));
        }
        asm volatile("cp.async.commit_group;");
    };

#pragma unroll
    for (int p = 0; p < NBUF - 1; p++) stage(p);

    for (int ii = 0; ii < 16; ++ii) {
        if (ii <= 16 - NBUF + 1) {
            asm volatile("cp.async.wait_group %0;" :: "n"(NBUF - 2));
        } else {
            asm volatile("cp.async.wait_group 0;");
        }
        __syncthreads();
        if (ii + NBUF - 1 < 16) stage(ii + NBUF - 1);

        const int il = ii * 8 + g;
        const float* x1r = xs1 + il * XR + KOFF;   // KOFF even -> 8B aligned
        const float* x2r = xs2 + il * XR + KOFF;

        // weight row -> packed {w,w} pairs (no scalar copy kept)
        const float* wrow = ws + (ii % NBUF) * BUF + tid * SP;
        unsigned long long ww[C4 * 4];
#pragma unroll
        for (int c = 0; c < C4; c++) {
            float4 w4 = *reinterpret_cast<const float4*>(wrow + c * 4);
            ww[c * 4 + 0] = pk2(w4.x, w4.x);
            ww[c * 4 + 1] = pk2(w4.y, w4.y);
            ww[c * 4 + 2] = pk2(w4.z, w4.z);
            ww[c * 4 + 3] = pk2(w4.w, w4.w);
        }

#pragma unroll
        for (int tp = 0; tp < L2; tp++) {
#pragma unroll
            for (int h = 0; h < K; h++) {
                unsigned long long xv = (h & 1)
                    ? *reinterpret_cast<const unsigned long long*>(x2r + 2 * (tp + (h - 1) / 2))
                    : *reinterpret_cast<const unsigned long long*>(x1r + 2 * (tp + h / 2));
                fma2(acc2[tp], xv, ww[h]);
            }
        }
        if constexpr (L & 1) {
#pragma unroll
            for (int h = 0; h < K; h++) {
                float wlo, whi;
                upk2(wlo, whi, ww[h]);
                accT = fmaf(x1r[L - 1 + h], wlo, accT);
            }
        }
        __syncwarp();
    }

#pragma unroll
    for (int tp = 0; tp < L2; tp++) {
        float a0, a1;
        upk2(a0, a1, acc2[tp]);
#pragma unroll
        for (int m = 1; m <= 4; m <<= 1) {
            a0 += __shfl_xor_sync(0xffffffffu, a0, m);
            a1 += __shfl_xor_sync(0xffffffffu, a1, m);
        }
        if (g == 0) {
            yout[(2 * tp) * 256 + o] = a0;
            yout[(2 * tp + 1) * 256 + o] = a1;
        }
    }
    if constexpr (L & 1) {
#pragma unroll
        for (int m = 1; m <= 4; m <<= 1)
            accT += __shfl_xor_sync(0xffffffffu, accT, m);
        if (g == 0) yout[(L - 1) * 256 + o] = accT;
    }
}

#define TOFF_OF(B) ((B) * 32 - ((B) * ((B) - 1)) / 2)

template<int B>
__device__ __forceinline__ void dispatch_full(
    int b, const float* __restrict__ cw,
    const float* __restrict__ xs1, const float* __restrict__ xs2,
    float* __restrict__ ws, int otile, int ihalf, int tid)
{
    if (b == B) {
        conv_branch<B + 1, 32 - B, 0>(cw + (size_t)B * (256 * 256 * 32),
                                      xs1, xs2, ws, otile, ihalf, tid,
                                      &g_ypart[ihalf][TOFF_OF(B) * 256]);
    } else if constexpr (B < 15) {
        dispatch_full<B + 1>(b, cw, xs1, xs2, ws, otile, ihalf, tid);
    }
}

template<int B>
__device__ __forceinline__ void dispatch_k1(
    int b, const float* __restrict__ cw,
    const float* __restrict__ xs1, const float* __restrict__ xs2,
    float* __restrict__ ws, int otile, int ihalf, int tid)
{
    if (b == B) {
        conv_branch<16, 32 - B, 0>(cw + (size_t)B * (256 * 256 * 32),
                                   xs1, xs2, ws, otile, ihalf, tid,
                                   &g_ypart[ihalf][TOFF_OF(B) * 256]);
    } else if constexpr (B < 31) {
        dispatch_k1<B + 1>(b, cw, xs1, xs2, ws, otile, ihalf, tid);
    }
}

template<int B>
__device__ __forceinline__ void dispatch_k2(
    int b, const float* __restrict__ cw,
    const float* __restrict__ xs1, const float* __restrict__ xs2,
    float* __restrict__ ws, int otile, int ihalf, int tid)
{
    if (b == B) {
        conv_branch<B - 15, 32 - B, 16>(cw + (size_t)B * (256 * 256 * 32),
                                        xs1, xs2, ws, otile, ihalf, tid,
                                        &g_ypart[2 + ihalf][TOFF_OF(B) * 256]);
    } else if constexpr (B < 31) {
        dispatch_k2<B + 1>(b, cw, xs1, xs2, ws, otile, ihalf, tid);
    }
}

// ---------------------------------------------------------------------------
// m-partial role (input-only): blocks 0..NQB-1 of the conv grid.
// ---------------------------------------------------------------------------
__device__ void m_role(
    const float* __restrict__ opw, const float* __restrict__ ipw,
    const float* __restrict__ ipb, int blk, int tid, float* __restrict__ a_sh)
{
    const int q0 = blk * QPB;
    float (*a_s)[QPB] = reinterpret_cast<float (*)[QPB]>(a_sh);

    if (tid < 4 * QPB) {
        int w = tid / QPB, qq = tid - w * QPB;
        float a = 0.0f;
        const float* base = opw + (size_t)(128 * w) * TT + (q0 + qq);
#pragma unroll
        for (int j = 0; j < 32; j++) a += base[(size_t)j * TT];
        a_s[w][qq] = a;
    }
    __syncthreads();

    const int t1 = tid, t2 = tid + 256, t3 = tid + 512;
    float acc[4][3] = {};
    for (int qq = 0; qq < QPB; qq++) {
        const float* row = ipw + (size_t)(2 * TT + q0 + qq) * TT;
        float v1 = row[t1];
        float v2 = row[t2];
        float v3 = (t3 < TT) ? row[t3] : 0.0f;
#pragma unroll
        for (int w = 0; w < 4; w++) {
            float aw = a_s[w][qq];
            acc[w][0] = fmaf(aw, v1, acc[w][0]);
            acc[w][1] = fmaf(aw, v2, acc[w][1]);
            acc[w][2] = fmaf(aw, v3, acc[w][2]);
        }
    }
#pragma unroll
    for (int w = 0; w < 4; w++) {
        g_mpart[blk][w][t1] = acc[w][0];
        g_mpart[blk][w][t2] = acc[w][1];
        if (t3 < TT) g_mpart[blk][w][t3] = acc[w][2];
    }
    if (tid < 4) {
        const int w = tid;
        float d = 0.0f;
        for (int qq = 0; qq < QPB; qq++)
            d += a_s[w][qq] * ipb[2 * TT + q0 + qq];
        g_ipbdot[blk][w] = d;
    }
}

__global__ void __launch_bounds__(256, 3) k_conv(
    const float* __restrict__ x, const float* __restrict__ cw,
    const float* __restrict__ opw, const float* __restrict__ ipw,
    const float* __restrict__ ipb)
{
    extern __shared__ float smem[];
    const int tid = threadIdx.x;

    if (blockIdx.x < NQB) {
        m_role(opw, ipw, ipb, blockIdx.x, tid, smem);
        return;
    }

    float* xs1 = smem;
    float* xs2 = smem + XS1_FLOATS;
    float* ws  = smem + XS_TOTAL;

    const int cb = blockIdx.x - NQB;     // 0..767
    const int unit = cb >> 4;            // 0..47
    const int sub = cb & 15;
    const int otile = sub >> 1;
    const int ihalf = sub & 1;

    // transpose-stage x (+1-tau shifted copy)
    for (int idx = tid; idx < 4096; idx += 256) {
        int j = idx >> 7;
        int il = idx & 127;
        float v = x[j * 256 + ihalf * 128 + il];
        xs1[il * XR + j] = v;
        if (j > 0) xs2[il * XR + (j - 1)] = v;
    }
    __syncthreads();

    if (unit < 32) {
        if ((unit & 1) == 0) {
            dispatch_full<0>(15 - (unit >> 1), cw, xs1, xs2, ws, otile, ihalf, tid);
        } else {
            dispatch_k1<16>(16 + (unit >> 1), cw, xs1, xs2, ws, otile, ihalf, tid);
        }
    } else {
        dispatch_k2<16>(16 + (unit - 32), cw, xs1, xs2, ws, otile, ihalf, tid);
    }
}

// ---------------------------------------------------------------------------
// kA: per (branch, o-group of 32) partial gelu stats {s, s2}.
// 256 blocks x 256 threads; thread = (tg=warp, o-lane); t = tg*4..+4.
// ---------------------------------------------------------------------------
__global__ void __launch_bounds__(256) kA(const float* __restrict__ conv_b)
{
    const int b = blockIdx.x >> 3;
    const int og = blockIdx.x & 7;
    const int tid = threadIdx.x;
    const int tg = tid >> 5, lane = tid & 31;
    const int o = og * 32 + lane;
    const int L = 32 - b;
    const int toff = TOFF_OF(b);
    const bool four = (b >= 16);
    const float cbv = conv_b[b * 256 + o];

    float s = 0.0f, s2 = 0.0f;
#pragma unroll
    for (int k = 0; k < 4; k++) {
        int t = tg * 4 + k;
        if (t < L) {
            int idx = (toff + t) * 256 + o;
            float val = g_ypart[0][idx] + g_ypart[1][idx] + cbv;
            if (four) val += g_ypart[2][idx] + g_ypart[3][idx];
            float ge = 0.5f * val * (1.0f + erff(val * 0.70710678118654752440f));
            s += ge;
            s2 += ge * ge;
        }
    }
#pragma unroll
    for (int m = 16; m > 0; m >>= 1) {
        s  += __shfl_xor_sync(0xffffffffu, s, m);
        s2 += __shfl_xor_sync(0xffffffffu, s2, m);
    }
    __shared__ float shs[8], shs2[8];
    if (lane == 0) { shs[tg] = s; shs2[tg] = s2; }
    __syncthreads();
    if (tid == 0) {
        float a = 0.0f, a2 = 0.0f;
#pragma unroll
        for (int j = 0; j < 8; j++) { a += shs[j]; a2 += shs2[j]; }
        g_sp[b][og][0] = a;
        g_sp[b][og][1] = a2;
    }
}

// ---------------------------------------------------------------------------
// kB: 128 blocks (b x tg of 8 t) x 256 threads (o).
// mu/rs from g_sp; gelu recompute; ln; u[t]; pdot partial; last-block finish.
// ---------------------------------------------------------------------------
__global__ void __launch_bounds__(256) kB(
    const float* __restrict__ conv_b,
    const float* __restrict__ lnw, const float* __restrict__ lnb,
    const float* __restrict__ opb, float* __restrict__ out)
{
    const int b = blockIdx.x >> 2;
    const int tg = blockIdx.x & 3;
    const int tid = threadIdx.x;
    const int warpIdx = tid >> 5, lane = tid & 31;
    const int o = tid;
    const int L = 32 - b;
    const int toff = TOFF_OF(b);
    const bool four = (b >= 16);

    // mu / rs (uniform; every thread computes the same fixed-order sum)
    float a = 0.0f, a2 = 0.0f;
#pragma unroll
    for (int j = 0; j < 8; j++) { a += g_sp[b][j][0]; a2 += g_sp[b][j][1]; }
    const float inv = 1.0f / (float)(256 * L);
    const float mu = a * inv;
    const float rs = rsqrtf(a2 * inv - mu * mu + 1e-5f);

    const float cbv = conv_b[b * 256 + o];
    const float* lwp = lnw + ((size_t)b * 256 + o) * 32;
    const float* lbp = lnb + ((size_t)b * 256 + o) * 32;

    __shared__ float red[8][9];
#pragma unroll
    for (int k = 0; k < 8; k++) {
        int t = tg * 8 + k;
        float c = 0.0f;
        if (t < L) {
            int idx = (toff + t) * 256 + o;
            float val = g_ypart[0][idx] + g_ypart[1][idx] + cbv;
            if (four) val += g_ypart[2][idx] + g_ypart[3][idx];
            float ge = 0.5f * val * (1.0f + erff(val * 0.70710678118654752440f));
            c = fmaf((ge - mu) * rs, lwp[t], lbp[t]);
        }
#pragma unroll
        for (int m = 16; m > 0; m >>= 1) c += __shfl_xor_sync(0xffffffffu, c, m);
        if (lane == 0) red[k][warpIdx] = c;
    }
    __syncthreads();

    // warps 0..3: w = warpIdx; lanes 0..7 = k; u then pdot partial
    if (warpIdx < 4) {
        const int w = warpIdx;
        float pd = 0.0f;
        if (lane < 8) {
            int t = tg * 8 + lane;
            if (t < L) {
                float u = 0.0f;
#pragma unroll
                for (int j = 0; j < 8; j++) u += red[lane][j];
                float m = 0.0f;
#pragma unroll
                for (int blk = 0; blk < NQB; blk++) m += g_mpart[blk][w][toff + t];
                pd = u * m;
            }
        }
#pragma unroll
        for (int mm = 16; mm > 0; mm >>= 1) pd += __shfl_xor_sync(0xffffffffu, pd, mm);
        if (lane == 0) g_pdot2[b * 4 + tg][w] = pd;
    }
    __threadfence();
    __syncthreads();

    __shared__ int s_last;
    if (tid == 0) s_last = (atomicAdd(&g_cnt, 1) == 127) ? 1 : 0;
    __syncthreads();
    if (s_last == 0) return;
    __threadfence();

    // finalize: out_w = (1/32)(sum_l pdot2[l][w] + 256*sum ipbdot + 256*sum opb)
    __shared__ float tot[4];
    {
        const int w = tid >> 6;
        const int l = tid & 63;
        float v = g_pdot2[l][w] + g_pdot2[l + 64][w];
        if (l < NQB) v += 256.0f * g_ipbdot[l][w];
        if (l < 32) v += 256.0f * opb[128 * w + l];
        // reduce 64 lanes (2 warps) per w
#pragma unroll
        for (int m = 16; m > 0; m >>= 1) v += __shfl_xor_sync(0xffffffffu, v, m);
        __shared__ float part[8];
        if ((tid & 31) == 0) part[tid >> 5] = v;
        __syncthreads();
        if (tid < 4) tot[tid] = (part[2 * tid] + part[2 * tid + 1]) * (1.0f / 32.0f);
    }
    __syncthreads();
    for (int idx = tid; idx < 1024; idx += 256) out[idx] = tot[idx >> 8];
    if (tid == 0) g_cnt = 0;
}

// ---------------------------------------------------------------------------
extern "C" void kernel_launch(void* const* d_in, const int* in_sizes, int n_in,
                              void* d_out, int out_size)
{
    const float* x      = (const float*)d_in[0];
    const float* conv_w = (const float*)d_in[1];
    const float* conv_b = (const float*)d_in[2];
    const float* ln_w   = (const float*)d_in[3];
    const float* ln_b   = (const float*)d_in[4];
    const float* ipw    = (const float*)d_in[5];
    const float* ipb    = (const float*)d_in[6];
    const float* opw    = (const float*)d_in[7];
    const float* opb    = (const float*)d_in[8];
    float* out = (float*)d_out;

    cudaFuncSetAttribute(k_conv, cudaFuncAttributeMaxDynamicSharedMemorySize,
                         SMEM_BYTES);

    k_conv<<<768 + NQB, 256, SMEM_BYTES>>>(x, conv_w, opw, ipw, ipb);
    kA   <<<256, 256>>>(conv_b);
    kB   <<<128, 256>>>(conv_b, ln_w, ln_b, opb, out);

    (void)in_sizes; (void)n_in; (void)out_size;
}

// round 12
// speedup vs baseline: 1.9116x; 1.1924x over previous
#include <cuda_runtime.h>
#include <math.h>
#include <stddef.h>
#include <stdint.h>

// Problem constants: Dur=32, Dim=256, T=528
#define TT 528
#define NQB 24          // q-partial blocks for m (22 q each)
#define QPB 22

// Scratch (device globals: allocation-free)
// parts: 0,1 = ihalf{0,1} of taps 0..15 (or full K if K<=16); 2,3 = taps 16+
__device__ float g_ypart[4][256 * TT];
__device__ float g_mpart[NQB][4][TT];
__device__ float g_ipbdot[NQB][4];
__device__ float g_sp[32][8][2];        // per (branch, o-group) partial {s, s2}
__device__ float g_pdot2[128][4];       // per (branch*4+tg, w) partial u.m dot
__device__ int   g_cnt;                 // kB completion counter (self-reset)

// k_conv shared: xs1/xs2 transposed x copies + 2..3 weight buffers (SP<=20)
#define XR 34
#define XS1_FLOATS (128 * XR)
#define XS_TOTAL (2 * XS1_FLOATS)       // 8704 floats = 34816 B
#define WS_BYTES 40960                  // 2 x 256 x 20 x 4
#define SMEM_BYTES (XS_TOTAL * 4 + WS_BYTES)   // 75776 B -> 3 blocks/SM

__device__ __forceinline__ uint32_t smem_u32(const void* p) {
    return (uint32_t)__cvta_generic_to_shared(p);
}
__device__ __forceinline__ unsigned long long pk2(float lo, float hi) {
    unsigned long long r;
    asm("mov.b64 %0, {%1, %2};" : "=l"(r) : "f"(lo), "f"(hi));
    return r;
}
__device__ __forceinline__ void upk2(float& lo, float& hi, unsigned long long v) {
    asm("mov.b64 {%0, %1}, %2;" : "=f"(lo), "=f"(hi) : "l"(v));
}
__device__ __forceinline__ void fma2(unsigned long long& d,
                                     unsigned long long a, unsigned long long b) {
    asm("fma.rn.f32x2 %0, %1, %2, %0;" : "+l"(d) : "l"(a), "l"(b));
}

// ---------------------------------------------------------------------------
// Conv sub-branch: taps [KOFF, KOFF+K) of a branch with output length L.
// K <= 16 always (K-split). f32x2 over t-pairs; weights cp.async pipelined.
// ---------------------------------------------------------------------------
template<int K, int L, int KOFF>
__device__ __forceinline__ void conv_branch(
    const float* __restrict__ wB,
    const float* __restrict__ xs1, const float* __restrict__ xs2,
    float* __restrict__ ws,
    int otile, int ihalf, int tid,
    float* __restrict__ yout)
{
    constexpr int C4 = (K + 3) / 4;                  // <= 4
    constexpr int SP = C4 * 4 + ((C4 & 1) ? 8 : 4);  // 12 or 20, %8==4
    constexpr int NBUF = (C4 <= 2) ? 3 : 2;          // fits WS_BYTES
    constexpr int BUF = 256 * SP;
    constexpr int L2 = L / 2;

    const int g = tid & 7;
    const int o = otile * 32 + (tid >> 3);

    unsigned long long acc2[L2 > 0 ? L2 : 1];
#pragma unroll
    for (int t = 0; t < L2; t++) acc2[t] = 0ull;
    float accT = 0.0f;

    auto stage = [&](int ii) {
        const int ibase = ihalf * 128 + ii * 8;
        const uint32_t wsb = smem_u32(ws + (ii % NBUF) * BUF);
#pragma unroll
        for (int k = 0; k < C4; k++) {
            int idx = tid + 256 * k;
            int r = idx / C4;
            int c = idx - r * C4;
            const float* src = wB + (size_t)(otile * 32 + (r >> 3)) * 8192
                                  + (size_t)(ibase + (r & 7)) * 32 + KOFF + c * 4;
            asm volatile("cp.async.cg.shared.global [%0], [%1], 16;"
                         :: "r"(wsb + (uint32_t)(r * SP + c * 4) * 4), "l"(src));
        }
        asm volatile("cp.async.commit_group;");
    };

#pragma unroll
    for (int p = 0; p < NBUF - 1; p++) stage(p);

    for (int ii = 0; ii < 16; ++ii) {
        if (ii <= 16 - NBUF + 1) {
            asm volatile("cp.async.wait_group %0;" :: "n"(NBUF - 2));
        } else {
            asm volatile("cp.async.wait_group 0;");
        }
        __syncthreads();
        if (ii + NBUF - 1 < 16) stage(ii + NBUF - 1);

        const int il = ii * 8 + g;
        const float* x1r = xs1 + il * XR + KOFF;   // KOFF even -> 8B aligned
        const float* x2r = xs2 + il * XR + KOFF;

        // weight row -> packed {w,w} pairs
        const float* wrow = ws + (ii % NBUF) * BUF + tid * SP;
        unsigned long long ww[C4 * 4];
#pragma unroll
        for (int c = 0; c < C4; c++) {
            float4 w4 = *reinterpret_cast<const float4*>(wrow + c * 4);
            ww[c * 4 + 0] = pk2(w4.x, w4.x);
            ww[c * 4 + 1] = pk2(w4.y, w4.y);
            ww[c * 4 + 2] = pk2(w4.z, w4.z);
            ww[c * 4 + 3] = pk2(w4.w, w4.w);
        }

#pragma unroll
        for (int tp = 0; tp < L2; tp++) {
#pragma unroll
            for (int h = 0; h < K; h++) {
                unsigned long long xv = (h & 1)
                    ? *reinterpret_cast<const unsigned long long*>(x2r + 2 * (tp + (h - 1) / 2))
                    : *reinterpret_cast<const unsigned long long*>(x1r + 2 * (tp + h / 2));
                fma2(acc2[tp], xv, ww[h]);
            }
        }
        if constexpr (L & 1) {
#pragma unroll
            for (int h = 0; h < K; h++) {
                float wlo, whi;
                upk2(wlo, whi, ww[h]);
                accT = fmaf(x1r[L - 1 + h], wlo, accT);
            }
        }
        __syncwarp();
    }

#pragma unroll
    for (int tp = 0; tp < L2; tp++) {
        float a0, a1;
        upk2(a0, a1, acc2[tp]);
#pragma unroll
        for (int m = 1; m <= 4; m <<= 1) {
            a0 += __shfl_xor_sync(0xffffffffu, a0, m);
            a1 += __shfl_xor_sync(0xffffffffu, a1, m);
        }
        if (g == 0) {
            yout[(2 * tp) * 256 + o] = a0;
            yout[(2 * tp + 1) * 256 + o] = a1;
        }
    }
    if constexpr (L & 1) {
#pragma unroll
        for (int m = 1; m <= 4; m <<= 1)
            accT += __shfl_xor_sync(0xffffffffu, accT, m);
        if (g == 0) yout[(L - 1) * 256 + o] = accT;
    }
}

#define TOFF_OF(B) ((B) * 32 - ((B) * ((B) - 1)) / 2)

template<int B>
__device__ __forceinline__ void dispatch_full(
    int b, const float* __restrict__ cw,
    const float* __restrict__ xs1, const float* __restrict__ xs2,
    float* __restrict__ ws, int otile, int ihalf, int tid)
{
    if (b == B) {
        conv_branch<B + 1, 32 - B, 0>(cw + (size_t)B * (256 * 256 * 32),
                                      xs1, xs2, ws, otile, ihalf, tid,
                                      &g_ypart[ihalf][TOFF_OF(B) * 256]);
    } else if constexpr (B < 15) {
        dispatch_full<B + 1>(b, cw, xs1, xs2, ws, otile, ihalf, tid);
    }
}

template<int B>
__device__ __forceinline__ void dispatch_k1(
    int b, const float* __restrict__ cw,
    const float* __restrict__ xs1, const float* __restrict__ xs2,
    float* __restrict__ ws, int otile, int ihalf, int tid)
{
    if (b == B) {
        conv_branch<16, 32 - B, 0>(cw + (size_t)B * (256 * 256 * 32),
                                   xs1, xs2, ws, otile, ihalf, tid,
                                   &g_ypart[ihalf][TOFF_OF(B) * 256]);
    } else if constexpr (B < 31) {
        dispatch_k1<B + 1>(b, cw, xs1, xs2, ws, otile, ihalf, tid);
    }
}

template<int B>
__device__ __forceinline__ void dispatch_k2(
    int b, const float* __restrict__ cw,
    const float* __restrict__ xs1, const float* __restrict__ xs2,
    float* __restrict__ ws, int otile, int ihalf, int tid)
{
    if (b == B) {
        conv_branch<B - 15, 32 - B, 16>(cw + (size_t)B * (256 * 256 * 32),
                                        xs1, xs2, ws, otile, ihalf, tid,
                                        &g_ypart[2 + ihalf][TOFF_OF(B) * 256]);
    } else if constexpr (B < 31) {
        dispatch_k2<B + 1>(b, cw, xs1, xs2, ws, otile, ihalf, tid);
    }
}

// ---------------------------------------------------------------------------
// m-partial role (input-only): blocks 0..NQB-1 of the conv grid.
// ---------------------------------------------------------------------------
__device__ void m_role(
    const float* __restrict__ opw, const float* __restrict__ ipw,
    const float* __restrict__ ipb, int blk, int tid, float* __restrict__ a_sh)
{
    const int q0 = blk * QPB;
    float (*a_s)[QPB] = reinterpret_cast<float (*)[QPB]>(a_sh);

    if (tid < 4 * QPB) {
        int w = tid / QPB, qq = tid - w * QPB;
        float a = 0.0f;
        const float* base = opw + (size_t)(128 * w) * TT + (q0 + qq);
#pragma unroll
        for (int j = 0; j < 32; j++) a += base[(size_t)j * TT];
        a_s[w][qq] = a;
    }
    __syncthreads();

    const int t1 = tid, t2 = tid + 256, t3 = tid + 512;
    float acc[4][3] = {};
    for (int qq = 0; qq < QPB; qq++) {
        const float* row = ipw + (size_t)(2 * TT + q0 + qq) * TT;
        float v1 = row[t1];
        float v2 = row[t2];
        float v3 = (t3 < TT) ? row[t3] : 0.0f;
#pragma unroll
        for (int w = 0; w < 4; w++) {
            float aw = a_s[w][qq];
            acc[w][0] = fmaf(aw, v1, acc[w][0]);
            acc[w][1] = fmaf(aw, v2, acc[w][1]);
            acc[w][2] = fmaf(aw, v3, acc[w][2]);
        }
    }
#pragma unroll
    for (int w = 0; w < 4; w++) {
        g_mpart[blk][w][t1] = acc[w][0];
        g_mpart[blk][w][t2] = acc[w][1];
        if (t3 < TT) g_mpart[blk][w][t3] = acc[w][2];
    }
    if (tid < 4) {
        const int w = tid;
        float d = 0.0f;
        for (int qq = 0; qq < QPB; qq++)
            d += a_s[w][qq] * ipb[2 * TT + q0 + qq];
        g_ipbdot[blk][w] = d;
    }
}

__global__ void __launch_bounds__(256, 3) k_conv(
    const float* __restrict__ x, const float* __restrict__ cw,
    const float* __restrict__ opw, const float* __restrict__ ipw,
    const float* __restrict__ ipb)
{
    extern __shared__ float smem[];
    const int tid = threadIdx.x;

    if (blockIdx.x < NQB) {
        m_role(opw, ipw, ipb, blockIdx.x, tid, smem);
        return;
    }

    float* xs1 = smem;
    float* xs2 = smem + XS1_FLOATS;
    float* ws  = smem + XS_TOTAL;

    const int cb = blockIdx.x - NQB;     // 0..767
    const int unit = cb >> 4;            // 0..47
    const int sub = cb & 15;
    const int otile = sub >> 1;
    const int ihalf = sub & 1;

    // transpose-stage x (+1-tau shifted copy)
    for (int idx = tid; idx < 4096; idx += 256) {
        int j = idx >> 7;
        int il = idx & 127;
        float v = x[j * 256 + ihalf * 128 + il];
        xs1[il * XR + j] = v;
        if (j > 0) xs2[il * XR + (j - 1)] = v;
    }
    __syncthreads();

    // L2-adjacency schedule: unit triplet i -> k1(16+i), k2(16+i), full(15-i).
    // k1/k2 of the same branch are co-resident -> their shared 128B weight
    // lines are fetched from DRAM once.
    const int i = unit / 3;
    const int r = unit - 3 * i;
    if (r == 0)      dispatch_k1<16>(16 + i, cw, xs1, xs2, ws, otile, ihalf, tid);
    else if (r == 1) dispatch_k2<16>(16 + i, cw, xs1, xs2, ws, otile, ihalf, tid);
    else             dispatch_full<0>(15 - i, cw, xs1, xs2, ws, otile, ihalf, tid);
}

// ---------------------------------------------------------------------------
// kA: per (branch, o-group of 32) partial gelu stats {s, s2}.
// ---------------------------------------------------------------------------
__global__ void __launch_bounds__(256) kA(const float* __restrict__ conv_b)
{
    const int b = blockIdx.x >> 3;
    const int og = blockIdx.x & 7;
    const int tid = threadIdx.x;
    const int tg = tid >> 5, lane = tid & 31;
    const int o = og * 32 + lane;
    const int L = 32 - b;
    const int toff = TOFF_OF(b);
    const bool four = (b >= 16);
    const float cbv = conv_b[b * 256 + o];

    float s = 0.0f, s2 = 0.0f;
#pragma unroll
    for (int k = 0; k < 4; k++) {
        int t = tg * 4 + k;
        if (t < L) {
            int idx = (toff + t) * 256 + o;
            float val = g_ypart[0][idx] + g_ypart[1][idx] + cbv;
            if (four) val += g_ypart[2][idx] + g_ypart[3][idx];
            float ge = 0.5f * val * (1.0f + erff(val * 0.70710678118654752440f));
            s += ge;
            s2 += ge * ge;
        }
    }
#pragma unroll
    for (int m = 16; m > 0; m >>= 1) {
        s  += __shfl_xor_sync(0xffffffffu, s, m);
        s2 += __shfl_xor_sync(0xffffffffu, s2, m);
    }
    __shared__ float shs[8], shs2[8];
    if (lane == 0) { shs[tg] = s; shs2[tg] = s2; }
    __syncthreads();
    if (tid == 0) {
        float a = 0.0f, a2 = 0.0f;
#pragma unroll
        for (int j = 0; j < 8; j++) { a += shs[j]; a2 += shs2[j]; }
        g_sp[b][og][0] = a;
        g_sp[b][og][1] = a2;
    }
}

// ---------------------------------------------------------------------------
// kB: 128 blocks (b x tg of 8 t) x 256 threads (o).
// ---------------------------------------------------------------------------
__global__ void __launch_bounds__(256) kB(
    const float* __restrict__ conv_b,
    const float* __restrict__ lnw, const float* __restrict__ lnb,
    const float* __restrict__ opb, float* __restrict__ out)
{
    const int b = blockIdx.x >> 2;
    const int tg = blockIdx.x & 3;
    const int tid = threadIdx.x;
    const int warpIdx = tid >> 5, lane = tid & 31;
    const int o = tid;
    const int L = 32 - b;
    const int toff = TOFF_OF(b);
    const bool four = (b >= 16);

    float a = 0.0f, a2 = 0.0f;
#pragma unroll
    for (int j = 0; j < 8; j++) { a += g_sp[b][j][0]; a2 += g_sp[b][j][1]; }
    const float inv = 1.0f / (float)(256 * L);
    const float mu = a * inv;
    const float rs = rsqrtf(a2 * inv - mu * mu + 1e-5f);

    const float cbv = conv_b[b * 256 + o];
    const float* lwp = lnw + ((size_t)b * 256 + o) * 32;
    const float* lbp = lnb + ((size_t)b * 256 + o) * 32;

    __shared__ float red[8][9];
#pragma unroll
    for (int k = 0; k < 8; k++) {
        int t = tg * 8 + k;
        float c = 0.0f;
        if (t < L) {
            int idx = (toff + t) * 256 + o;
            float val = g_ypart[0][idx] + g_ypart[1][idx] + cbv;
            if (four) val += g_ypart[2][idx] + g_ypart[3][idx];
            float ge = 0.5f * val * (1.0f + erff(val * 0.70710678118654752440f));
            c = fmaf((ge - mu) * rs, lwp[t], lbp[t]);
        }
#pragma unroll
        for (int m = 16; m > 0; m >>= 1) c += __shfl_xor_sync(0xffffffffu, c, m);
        if (lane == 0) red[k][warpIdx] = c;
    }
    __syncthreads();

    if (warpIdx < 4) {
        const int w = warpIdx;
        float pd = 0.0f;
        if (lane < 8) {
            int t = tg * 8 + lane;
            if (t < L) {
                float u = 0.0f;
#pragma unroll
                for (int j = 0; j < 8; j++) u += red[lane][j];
                float m = 0.0f;
#pragma unroll
                for (int blk = 0; blk < NQB; blk++) m += g_mpart[blk][w][toff + t];
                pd = u * m;
            }
        }
#pragma unroll
        for (int mm = 16; mm > 0; mm >>= 1) pd += __shfl_xor_sync(0xffffffffu, pd, mm);
        if (lane == 0) g_pdot2[b * 4 + tg][w] = pd;
    }
    __threadfence();
    __syncthreads();

    __shared__ int s_last;
    if (tid == 0) s_last = (atomicAdd(&g_cnt, 1) == 127) ? 1 : 0;
    __syncthreads();
    if (s_last == 0) return;
    __threadfence();

    __shared__ float tot[4];
    {
        const int w = tid >> 6;
        const int l = tid & 63;
        float v = g_pdot2[l][w] + g_pdot2[l + 64][w];
        if (l < NQB) v += 256.0f * g_ipbdot[l][w];
        if (l < 32) v += 256.0f * opb[128 * w + l];
#pragma unroll
        for (int m = 16; m > 0; m >>= 1) v += __shfl_xor_sync(0xffffffffu, v, m);
        __shared__ float part[8];
        if ((tid & 31) == 0) part[tid >> 5] = v;
        __syncthreads();
        if (tid < 4) tot[tid] = (part[2 * tid] + part[2 * tid + 1]) * (1.0f / 32.0f);
    }
    __syncthreads();
    for (int idx = tid; idx < 1024; idx += 256) out[idx] = tot[idx >> 8];
    if (tid == 0) g_cnt = 0;
}

// ---------------------------------------------------------------------------
extern "C" void kernel_launch(void* const* d_in, const int* in_sizes, int n_in,
                              void* d_out, int out_size)
{
    const float* x      = (const float*)d_in[0];
    const float* conv_w = (const float*)d_in[1];
    const float* conv_b = (const float*)d_in[2];
    const float* ln_w   = (const float*)d_in[3];
    const float* ln_b   = (const float*)d_in[4];
    const float* ipw    = (const float*)d_in[5];
    const float* ipb    = (const float*)d_in[6];
    const float* opw    = (const float*)d_in[7];
    const float* opb    = (const float*)d_in[8];
    float* out = (float*)d_out;

    cudaFuncSetAttribute(k_conv, cudaFuncAttributeMaxDynamicSharedMemorySize,
                         SMEM_BYTES);

    k_conv<<<768 + NQB, 256, SMEM_BYTES>>>(x, conv_w, opw, ipw, ipb);
    kA   <<<256, 256>>>(conv_b);
    kB   <<<128, 256>>>(conv_b, ln_w, ln_b, opb, out);

    (void)in_sizes; (void)n_in; (void)out_size;
}